// round 9
// baseline (speedup 1.0000x reference)
#include <cuda_runtime.h>
#include <cuda_bf16.h>
#include <cstdint>

#define Hd 128
#define MAXM 50048
#define MAXL 400128
#define SEPS 1e-9f
#define NT 512

// ---------------- scratch (device globals; no allocations) ----------------
__device__ float g_Bx [MAXM*Hd];
__device__ float g_Wix[MAXM*Hd];
__device__ float g_Wfx[MAXM*Hd];
__device__ float g_Wox[MAXM*Hd];
__device__ float g_Wcx[MAXM*Hd];
__device__ float g_Ah [MAXM*Hd];
__device__ float g_Ufh[MAXM*Hd];
__device__ float g_hhat[MAXM*Hd];
__device__ float g_sumfc[MAXM*Hd];
__device__ float g_e[MAXL];
__device__ float g_segsum[MAXM];
__device__ unsigned g_segmax[MAXM];
// pre-split, pre-swizzled weights: 10 x 128x128 bf16 (hi & lo), 32KB each
__device__ __align__(16) char g_Wbhi[10 * 32768];
__device__ __align__(16) char g_Wblo[10 * 32768];

// ---------------- scalar helpers ----------------
__device__ __forceinline__ float sigm_f(float x) {
    return __fdividef(1.0f, 1.0f + __expf(-x));
}
__device__ __forceinline__ float tanh_f(float x) {
    float e2 = __expf(2.0f * x);
    return 1.0f - __fdividef(2.0f, e2 + 1.0f);
}
__device__ __forceinline__ unsigned encf(float f) {
    unsigned b = __float_as_uint(f);
    return (b & 0x80000000u) ? ~b : (b | 0x80000000u);
}
__device__ __forceinline__ float decf(unsigned u) {
    return (u & 0x80000000u) ? __uint_as_float(u ^ 0x80000000u) : __uint_as_float(~u);
}
__device__ __forceinline__ void red4(float* p, float x, float y, float z, float w) {
    asm volatile("red.global.add.v4.f32 [%0], {%1, %2, %3, %4};"
                 :: "l"(p), "f"(x), "f"(y), "f"(z), "f"(w) : "memory");
}
__device__ __forceinline__ uint32_t smem_u32(const void* p) {
    uint32_t a;
    asm("{ .reg .u64 t; cvta.to.shared.u64 t, %1; cvt.u32.u64 %0, t; }" : "=r"(a) : "l"(p));
    return a;
}

// ---------------- mma / ldmatrix wrappers ----------------
__device__ __forceinline__ void ldm4(uint32_t* r, uint32_t addr) {
    asm volatile("ldmatrix.sync.aligned.m8n8.x4.shared.b16 {%0,%1,%2,%3}, [%4];"
                 : "=r"(r[0]), "=r"(r[1]), "=r"(r[2]), "=r"(r[3]) : "r"(addr));
}
__device__ __forceinline__ void mma16816(float* d, const uint32_t* a, const uint32_t* b) {
    asm volatile("mma.sync.aligned.m16n8k16.row.col.f32.bf16.bf16.f32 "
                 "{%0,%1,%2,%3}, {%4,%5,%6,%7}, {%8,%9}, {%0,%1,%2,%3};"
                 : "+f"(d[0]), "+f"(d[1]), "+f"(d[2]), "+f"(d[3])
                 : "r"(a[0]), "r"(a[1]), "r"(a[2]), "r"(a[3]), "r"(b[0]), "r"(b[1]));
}

// swizzled byte offset of (row, colbyte) in a 128-row x 256B tile
__device__ __forceinline__ uint32_t swz(int row, int colbyte) {
    return (uint32_t)(row * 256 + (colbyte ^ ((row & 7) << 4)));
}
__device__ __forceinline__ void split2(float x, float y, uint32_t& hp, uint32_t& lp) {
    __nv_bfloat16 hx = __float2bfloat16(x);
    __nv_bfloat16 hy = __float2bfloat16(y);
    __nv_bfloat16 lx = __float2bfloat16(x - __bfloat162float(hx));
    __nv_bfloat16 ly = __float2bfloat16(y - __bfloat162float(hy));
    hp = ((uint32_t)__bfloat16_as_ushort(hy) << 16) | __bfloat16_as_ushort(hx);
    lp = ((uint32_t)__bfloat16_as_ushort(ly) << 16) | __bfloat16_as_ushort(lx);
}

// ---------------- prep: zero accumulators + pre-split all 10 weights ----------------
struct PrepArgs { const float* W[10]; };

__global__ void prep_kernel(PrepArgs pa, int M) {
    int stride = gridDim.x * blockDim.x;
    int gt = blockIdx.x * blockDim.x + threadIdx.x;
    int n4 = M * Hd / 4;
    float4 z = make_float4(0.f, 0.f, 0.f, 0.f);
    for (int i = gt; i < n4; i += stride) {
        ((float4*)g_hhat)[i]  = z;
        ((float4*)g_sumfc)[i] = z;
    }
    for (int i = gt; i < M; i += stride) {
        g_segsum[i] = 0.f;
        g_segmax[i] = 0u;
    }
    for (int idx = gt; idx < 10 * 8192; idx += stride) {
        int w = idx >> 13;
        int i = idx & 8191;
        int row = i >> 6;
        int c2 = i & 63;
        float2 v = *(const float2*)(pa.W[w] + (size_t)row * Hd + c2 * 2);
        uint32_t hp, lp;
        split2(v.x, v.y, hp, lp);
        uint32_t off = swz(row, c2 * 4);
        *(uint32_t*)(g_Wbhi + w * 32768 + off) = hp;
        *(uint32_t*)(g_Wblo + w * 32768 + off) = lp;
    }
}

// ---------------- shared GEMM building blocks ----------------
#define SA_HI 0
#define SA_LO 32768
#define SW_HI 65536
#define SW_LO 98304
#define S_BIAS 131072
#define S_TOT1 (131072 + 512)
// fused kernel: Gu staging aliases the SW region (dead between gemm_core and
// next copy_w); Gs gate-state sits above. pitch 132 floats (conflict-free).
#define GPITCH 132
#define F_GU   65536
#define F_GS   135168
#define S_TOT3 (135168 + 128 * GPITCH * 4)

__device__ __forceinline__ void conv_tile(const float* __restrict__ A, int m0, int M,
                                          char* hi, char* lo, int tid) {
#pragma unroll
    for (int it = 0; it < 8192 / NT; it++) {
        int i = tid + it * NT;
        int row = i >> 6;
        int c2 = i & 63;
        float2 v = make_float2(0.f, 0.f);
        if (m0 + row < M) v = *(const float2*)(A + (size_t)(m0 + row) * Hd + c2 * 2);
        uint32_t hp, lp;
        split2(v.x, v.y, hp, lp);
        uint32_t off = swz(row, c2 * 4);
        *(uint32_t*)(hi + off) = hp;
        *(uint32_t*)(lo + off) = lp;
    }
}

__device__ __forceinline__ void copy_w(char* sm, const char* whi, const char* wlo, int tid) {
    const uint4* shi = (const uint4*)whi;
    const uint4* slo = (const uint4*)wlo;
#pragma unroll
    for (int it = 0; it < 2048 / NT; it++) {
        int i = tid + it * NT;
        ((uint4*)(sm + SW_HI))[i] = shi[i];
        ((uint4*)(sm + SW_LO))[i] = slo[i];
    }
}

// compute 128x128 bf16x3 gemm tile into acc[2][4][4] (per-thread fragments)
__device__ __forceinline__ void gemm_core(const uint32_t smb, float acc[2][4][4],
                                          int arow0, int akb, int brow0, int bkb) {
#pragma unroll
    for (int ti = 0; ti < 2; ti++)
#pragma unroll
        for (int tj = 0; tj < 4; tj++)
#pragma unroll
            for (int k = 0; k < 4; k++) acc[ti][tj][k] = 0.f;

#pragma unroll
    for (int ks = 0; ks < 8; ks++) {
        const int kb0 = ks * 32;
        uint32_t ah[2][4], al[2][4], bh[2][4], bl[2][4];
#pragma unroll
        for (int ti = 0; ti < 2; ti++) {
            int row = arow0 + ti * 16;
            uint32_t off = swz(row, kb0 + akb);
            ldm4(ah[ti], smb + SA_HI + off);
            ldm4(al[ti], smb + SA_LO + off);
        }
#pragma unroll
        for (int tp = 0; tp < 2; tp++) {
            int row = brow0 + tp * 16;
            uint32_t off = swz(row, kb0 + bkb);
            ldm4(bh[tp], smb + SW_HI + off);
            ldm4(bl[tp], smb + SW_LO + off);
        }
#pragma unroll
        for (int ti = 0; ti < 2; ti++)
#pragma unroll
            for (int tj = 0; tj < 4; tj++) {
                const uint32_t* bhp = &bh[tj >> 1][(tj & 1) * 2];
                const uint32_t* blp = &bl[tj >> 1][(tj & 1) * 2];
                mma16816(acc[ti][tj], ah[ti], bhp);
                mma16816(acc[ti][tj], ah[ti], blp);
                mma16816(acc[ti][tj], al[ti], bhp);
            }
    }
}

// ---------------- phase-1 GEMM: 7 weights, plain C outputs ----------------
struct TcArgs {
    const float* A1;
    const float* A2;
    const char* whi[7];
    const char* wlo[7];
    const float* b[7];
    float* C[7];
    int nW1, nW2, M;
};

__global__ void __launch_bounds__(NT, 1) gemm_mma(TcArgs ga) {
    extern __shared__ char sm[];
    const uint32_t smb = smem_u32(sm);
    const int tid = threadIdx.x;
    const int wid = tid >> 5;
    const int lane = tid & 31;
    const int m0 = blockIdx.x * 128;
    const int M = ga.M;
    const int wm = wid >> 2;
    const int wn = wid & 3;
    const int sub = lane & 7;
    const int quad = lane >> 3;
    const int arow0 = wm * 32 + sub + (quad & 1) * 8;
    const int akb   = (quad >> 1) * 16;
    const int brow0 = wn * 32 + sub + (quad >> 1) * 8;
    const int bkb   = (quad & 1) * 16;

    const float* Acur = ga.A1;
    int nW = ga.nW1;
    int wbase = 0;

    for (int sec = 0; sec < 2; sec++) {
        if (nW == 0) break;
        __syncthreads();
        conv_tile(Acur, m0, M, sm + SA_HI, sm + SA_LO, tid);

        for (int wi = 0; wi < nW; wi++) {
            const int w = wbase + wi;
            __syncthreads();
            copy_w(sm, ga.whi[w], ga.wlo[w], tid);
            if (tid < 128) ((float*)(sm + S_BIAS))[tid] = ga.b[w] ? __ldg(ga.b[w] + tid) : 0.f;
            __syncthreads();

            float acc[2][4][4];
            gemm_core(smb, acc, arow0, akb, brow0, bkb);

            const int g = lane >> 2;
            const int tg = lane & 3;
            float* __restrict__ C = ga.C[w];
            const float* sb = (const float*)(sm + S_BIAS);
#pragma unroll
            for (int ti = 0; ti < 2; ti++)
#pragma unroll
                for (int tj = 0; tj < 4; tj++) {
                    int row = m0 + wm * 32 + ti * 16 + g;
                    int col = wn * 32 + tj * 8 + tg * 2;
                    float2 bv = *(const float2*)(sb + col);
                    if (row < M)
                        *(float2*)(C + (size_t)row * Hd + col) =
                            make_float2(acc[ti][tj][0] + bv.x, acc[ti][tj][1] + bv.y);
                    if (row + 8 < M)
                        *(float2*)(C + (size_t)(row + 8) * Hd + col) =
                            make_float2(acc[ti][tj][2] + bv.x, acc[ti][tj][3] + bv.y);
                }
        }
        wbase += nW;
        Acur = ga.A2;
        nW = ga.nW2;
    }
}

// ---------------- phase-3 fused GEMM + streaming gate epilogue ----------------
// W sequence: Ui, Uc, Uo on A = hhat. Gates use Wix/Wcx/Wox (bias already in) + sumfc.
struct FusedArgs {
    const char* whi[3];
    const char* wlo[3];
    float* outh;
    float* outc;
    int M;
};

__global__ void __launch_bounds__(NT, 1) gemm_fused3(FusedArgs fa) {
    extern __shared__ char sm[];
    const uint32_t smb = smem_u32(sm);
    float* Gu = (float*)(sm + F_GU);
    float* Gs = (float*)(sm + F_GS);
    const int tid = threadIdx.x;
    const int wid = tid >> 5;
    const int lane = tid & 31;
    const int m0 = blockIdx.x * 128;
    const int M = fa.M;
    const int wm = wid >> 2;
    const int wn = wid & 3;
    const int sub = lane & 7;
    const int quad = lane >> 3;
    const int arow0 = wm * 32 + sub + (quad & 1) * 8;
    const int akb   = (quad >> 1) * 16;
    const int brow0 = wn * 32 + sub + (quad >> 1) * 8;
    const int bkb   = (quad & 1) * 16;
    const int g = lane >> 2;
    const int tg = lane & 3;

    conv_tile(g_hhat, m0, M, sm + SA_HI, sm + SA_LO, tid);

    for (int w = 0; w < 3; w++) {
        __syncthreads();             // prior stream's Gu reads / conv writes settled
        copy_w(sm, fa.whi[w], fa.wlo[w], tid);
        __syncthreads();

        float acc[2][4][4];
        gemm_core(smb, acc, arow0, akb, brow0, bkb);

        __syncthreads();             // all warps done reading SW before staging overwrites it
        // stage fragments -> Gu (aliases SW region)
#pragma unroll
        for (int ti = 0; ti < 2; ti++)
#pragma unroll
            for (int tj = 0; tj < 4; tj++) {
                int rl = wm * 32 + ti * 16 + g;
                int col = wn * 32 + tj * 8 + tg * 2;
                *(float2*)(Gu + rl * GPITCH + col) =
                    make_float2(acc[ti][tj][0], acc[ti][tj][1]);
                *(float2*)(Gu + (rl + 8) * GPITCH + col) =
                    make_float2(acc[ti][tj][2], acc[ti][tj][3]);
            }
        __syncthreads();

        // streaming gate math: 4096 float4 groups, 8 per thread, MLP-rich
#pragma unroll
        for (int it = 0; it < 4096 / NT; it++) {
            int i = tid + it * NT;
            int row = i >> 5;
            int col = (i & 31) * 4;
            int gidx = row * GPITCH + col;
            float4 u = *(const float4*)(Gu + gidx);
            size_t go = (size_t)(m0 + row) * Hd + col;
            bool ok = (m0 + row) < M;
            if (w == 0) {
                float4 wx = ok ? *(const float4*)(g_Wix + go) : make_float4(0.f, 0.f, 0.f, 0.f);
                float4 o;
                o.x = sigm_f(wx.x + u.x);
                o.y = sigm_f(wx.y + u.y);
                o.z = sigm_f(wx.z + u.z);
                o.w = sigm_f(wx.w + u.w);
                *(float4*)(Gs + gidx) = o;
            } else if (w == 1) {
                float4 wx = ok ? *(const float4*)(g_Wcx + go) : make_float4(0.f, 0.f, 0.f, 0.f);
                float4 sf = ok ? *(const float4*)(g_sumfc + go) : make_float4(0.f, 0.f, 0.f, 0.f);
                float4 ig = *(const float4*)(Gs + gidx);
                float4 cv;
                cv.x = fmaf(ig.x, tanh_f(wx.x + u.x), sf.x);
                cv.y = fmaf(ig.y, tanh_f(wx.y + u.y), sf.y);
                cv.z = fmaf(ig.z, tanh_f(wx.z + u.z), sf.z);
                cv.w = fmaf(ig.w, tanh_f(wx.w + u.w), sf.w);
                if (ok) *(float4*)(fa.outc + go) = cv;
                float4 tc;
                tc.x = tanh_f(cv.x);
                tc.y = tanh_f(cv.y);
                tc.z = tanh_f(cv.z);
                tc.w = tanh_f(cv.w);
                *(float4*)(Gs + gidx) = tc;
            } else {
                float4 wx = ok ? *(const float4*)(g_Wox + go) : make_float4(0.f, 0.f, 0.f, 0.f);
                float4 tc = *(const float4*)(Gs + gidx);
                if (ok) {
                    float4 h;
                    h.x = sigm_f(wx.x + u.x) * tc.x;
                    h.y = sigm_f(wx.y + u.y) * tc.y;
                    h.z = sigm_f(wx.z + u.z) * tc.z;
                    h.w = sigm_f(wx.w + u.w) * tc.w;
                    *(float4*)(fa.outh + go) = h;
                }
            }
        }
    }
}

// ---------------- pair pass 1 ----------------
__global__ void pair_e_kernel(const int* __restrict__ ci, const int* __restrict__ chi,
                              const float* __restrict__ v, int L) {
    __shared__ float vs[Hd];
    if (threadIdx.x < Hd) vs[threadIdx.x] = v[threadIdx.x];
    __syncthreads();

    int w = blockIdx.x * (blockDim.x >> 5) + (threadIdx.x >> 5);
    int lane = threadIdx.x & 31;
    if (w >= L) return;

    int c  = __ldg(ci + w);
    int ch = __ldg(chi + w);
    float4 a  = *(const float4*)(g_Ah + (size_t)ch * Hd + lane * 4);
    float4 b  = *(const float4*)(g_Bx + (size_t)c * Hd + lane * 4);
    float4 vv = *(const float4*)(vs + lane * 4);

    float s = tanh_f(a.x + b.x) * vv.x + tanh_f(a.y + b.y) * vv.y +
              tanh_f(a.z + b.z) * vv.z + tanh_f(a.w + b.w) * vv.w;
#pragma unroll
    for (int o = 16; o; o >>= 1) s += __shfl_xor_sync(0xFFFFFFFFu, s, o);

    if (lane == 0) {
        g_e[w] = s;
        atomicMax(g_segmax + c, encf(s));
    }
}

// ---------------- pair pass 2 ----------------
__global__ void pair_exp_kernel(const int* __restrict__ ci, int L) {
    int l = blockIdx.x * blockDim.x + threadIdx.x;
    if (l >= L) return;
    int c = ci[l];
    float mx = decf(g_segmax[c]);
    float xe = __expf(g_e[l] - mx);
    g_e[l] = xe;
    atomicAdd(g_segsum + c, xe);
}

// ---------------- pair pass 3 ----------------
__global__ void pair_acc_kernel(const float* __restrict__ child_h,
                                const float* __restrict__ child_c,
                                const int* __restrict__ ci, const int* __restrict__ chi,
                                int L) {
    int w = blockIdx.x * (blockDim.x >> 5) + (threadIdx.x >> 5);
    int lane = threadIdx.x & 31;
    if (w >= L) return;

    int c  = __ldg(ci + w);
    int ch = __ldg(chi + w);
    float attn = __ldg(g_e + w) / (__ldg(g_segsum + c) + SEPS);

    size_t co  = (size_t)c * Hd + lane * 4;
    size_t cho = (size_t)ch * Hd + lane * 4;

    float4 hv = *(const float4*)(child_h + cho);
    red4(g_hhat + co, attn * hv.x, attn * hv.y, attn * hv.z, attn * hv.w);

    float4 wf = *(const float4*)(g_Wfx + co);
    float4 uf = *(const float4*)(g_Ufh + cho);
    float4 cv = *(const float4*)(child_c + cho);
    float fx = sigm_f(wf.x + uf.x) * cv.x;
    float fy = sigm_f(wf.y + uf.y) * cv.y;
    float fz = sigm_f(wf.z + uf.z) * cv.z;
    float fw = sigm_f(wf.w + uf.w) * cv.w;
    red4(g_sumfc + co, fx, fy, fz, fw);
}

// ---------------- launch ----------------
extern "C" void kernel_launch(void* const* d_in, const int* in_sizes, int n_in,
                              void* d_out, int out_size) {
    const float* x_emb   = (const float*)d_in[0];
    const float* child_h = (const float*)d_in[1];
    const float* child_c = (const float*)d_in[2];
    const int*   ci      = (const int*)d_in[3];
    const int*   chi     = (const int*)d_in[4];
    const float* Wi_w = (const float*)d_in[5];
    const float* Ui_w = (const float*)d_in[6];
    const float* Wf_w = (const float*)d_in[7];
    const float* Uf_w = (const float*)d_in[8];
    const float* Wo_w = (const float*)d_in[9];
    const float* Uo_w = (const float*)d_in[10];
    const float* Wc_w = (const float*)d_in[11];
    const float* Uc_w = (const float*)d_in[12];
    const float* Wa_w = (const float*)d_in[13];
    const float* Ua_w = (const float*)d_in[14];
    const float* Wi_b = (const float*)d_in[15];
    const float* Wf_b = (const float*)d_in[16];
    const float* Wo_b = (const float*)d_in[17];
    const float* Wc_b = (const float*)d_in[18];
    const float* Wa_b = (const float*)d_in[19];
    const float* v_w  = (const float*)d_in[20];

    const int M = in_sizes[0] / Hd;
    const int L = in_sizes[3];

    float *p_Bx, *p_Wix, *p_Wfx, *p_Wox, *p_Wcx, *p_Ah, *p_Ufh;
    cudaGetSymbolAddress((void**)&p_Bx,  g_Bx);
    cudaGetSymbolAddress((void**)&p_Wix, g_Wix);
    cudaGetSymbolAddress((void**)&p_Wfx, g_Wfx);
    cudaGetSymbolAddress((void**)&p_Wox, g_Wox);
    cudaGetSymbolAddress((void**)&p_Wcx, g_Wcx);
    cudaGetSymbolAddress((void**)&p_Ah,  g_Ah);
    cudaGetSymbolAddress((void**)&p_Ufh, g_Ufh);
    char *p_whi, *p_wlo;
    cudaGetSymbolAddress((void**)&p_whi, g_Wbhi);
    cudaGetSymbolAddress((void**)&p_wlo, g_Wblo);

    float* outh = (float*)d_out;
    float* outc = outh + (size_t)M * Hd;

    const int mtiles = (M + 127) / 128;

    cudaFuncSetAttribute(gemm_mma, cudaFuncAttributeMaxDynamicSharedMemorySize, S_TOT1);
    cudaFuncSetAttribute(gemm_fused3, cudaFuncAttributeMaxDynamicSharedMemorySize, S_TOT3);

    // weight order in g_Wb: 0:Ua 1:Wi 2:Wf 3:Wo 4:Wc 5:Wa 6:Uf 7:Ui 8:Uc 9:Uo
    {
        PrepArgs pa;
        pa.W[0] = Ua_w; pa.W[1] = Wi_w; pa.W[2] = Wf_w; pa.W[3] = Wo_w; pa.W[4] = Wc_w;
        pa.W[5] = Wa_w; pa.W[6] = Uf_w; pa.W[7] = Ui_w; pa.W[8] = Uc_w; pa.W[9] = Uo_w;
        prep_kernel<<<296, 256>>>(pa, M);
    }

    // phase 1: x-side (Bx, Wix, Wfx, Wox, Wcx) + child_h-side (Ah, Ufh)
    {
        TcArgs ga;
        ga.A1 = x_emb; ga.A2 = child_h; ga.nW1 = 5; ga.nW2 = 2; ga.M = M;
        int slot[7] = {0, 1, 2, 3, 4, 5, 6};
        const float* bs[7] = {nullptr, Wi_b, Wf_b, Wo_b, Wc_b, Wa_b, nullptr};
        float* cs[7] = {p_Bx, p_Wix, p_Wfx, p_Wox, p_Wcx, p_Ah, p_Ufh};
        for (int i = 0; i < 7; i++) {
            ga.whi[i] = p_whi + slot[i] * 32768;
            ga.wlo[i] = p_wlo + slot[i] * 32768;
            ga.b[i] = bs[i];
            ga.C[i] = cs[i];
        }
        gemm_mma<<<mtiles, NT, S_TOT1>>>(ga);
    }

    // attention + forget-gate pair passes
    pair_e_kernel<<<(L + 7) / 8, 256>>>(ci, chi, v_w, L);
    pair_exp_kernel<<<(L + 255) / 256, 256>>>(ci, L);
    pair_acc_kernel<<<(L + 7) / 8, 256>>>(child_h, child_c, ci, chi, L);

    // phase 3: fused h_hat GEMMs (Ui, Uc, Uo) + streaming gate epilogue -> outh/outc
    {
        FusedArgs fa;
        int slot[3] = {7, 8, 9};
        for (int i = 0; i < 3; i++) {
            fa.whi[i] = p_whi + slot[i] * 32768;
            fa.wlo[i] = p_wlo + slot[i] * 32768;
        }
        fa.outh = outh; fa.outc = outc; fa.M = M;
        gemm_fused3<<<mtiles, NT, S_TOT3>>>(fa);
    }
}

// round 10
// speedup vs baseline: 1.0800x; 1.0800x over previous
#include <cuda_runtime.h>
#include <cuda_bf16.h>
#include <cuda_fp16.h>
#include <cstdint>

#define Hd 128
#define MAXM 50048
#define MAXL 400128
#define SEPS 1e-9f
#define NT 512

// ---------------- scratch (device globals; no allocations) ----------------
__device__ float g_Wix[MAXM*Hd];
__device__ float g_Wox[MAXM*Hd];
__device__ float g_Wcx[MAXM*Hd];
__device__ float g_hhat[MAXM*Hd];
__device__ float g_sumfc[MAXM*Hd];
__device__ float g_Uih[MAXM*Hd];
__device__ float g_Uch[MAXM*Hd];
__device__ float g_Uoh[MAXM*Hd];
// fp16 pair-phase operands (sole consumers are the pair kernels)
__device__ __half g_Ahh [MAXM*Hd];
__device__ __half g_Bxh [MAXM*Hd];
__device__ __half g_Wfxh[MAXM*Hd];
__device__ __half g_Ufhh[MAXM*Hd];
__device__ __half g_chh [MAXM*Hd];   // fp16 shadow of child_h
__device__ float g_e[MAXL];
__device__ float g_segsum[MAXM];
__device__ unsigned g_segmax[MAXM];
// pre-split, pre-swizzled weights: 10 x 128x128 bf16 (hi & lo), 32KB each
__device__ __align__(16) char g_Wbhi[10 * 32768];
__device__ __align__(16) char g_Wblo[10 * 32768];

// ---------------- scalar helpers ----------------
__device__ __forceinline__ float sigm_f(float x) {
    return __fdividef(1.0f, 1.0f + __expf(-x));
}
__device__ __forceinline__ float tanh_f(float x) {
    float e2 = __expf(2.0f * x);
    return 1.0f - __fdividef(2.0f, e2 + 1.0f);
}
__device__ __forceinline__ unsigned encf(float f) {
    unsigned b = __float_as_uint(f);
    return (b & 0x80000000u) ? ~b : (b | 0x80000000u);
}
__device__ __forceinline__ float decf(unsigned u) {
    return (u & 0x80000000u) ? __uint_as_float(u ^ 0x80000000u) : __uint_as_float(~u);
}
__device__ __forceinline__ void red4(float* p, float x, float y, float z, float w) {
    asm volatile("red.global.add.v4.f32 [%0], {%1, %2, %3, %4};"
                 :: "l"(p), "f"(x), "f"(y), "f"(z), "f"(w) : "memory");
}
__device__ __forceinline__ uint32_t smem_u32(const void* p) {
    uint32_t a;
    asm("{ .reg .u64 t; cvta.to.shared.u64 t, %1; cvt.u32.u64 %0, t; }" : "=r"(a) : "l"(p));
    return a;
}
// load 4 halves (8B) -> 4 floats
__device__ __forceinline__ float4 ld_half4(const __half* p) {
    uint2 v = *(const uint2*)p;
    float2 lo = __half22float2(*(__half2*)&v.x);
    float2 hi = __half22float2(*(__half2*)&v.y);
    return make_float4(lo.x, lo.y, hi.x, hi.y);
}

// ---------------- mma / ldmatrix wrappers ----------------
__device__ __forceinline__ void ldm4(uint32_t* r, uint32_t addr) {
    asm volatile("ldmatrix.sync.aligned.m8n8.x4.shared.b16 {%0,%1,%2,%3}, [%4];"
                 : "=r"(r[0]), "=r"(r[1]), "=r"(r[2]), "=r"(r[3]) : "r"(addr));
}
__device__ __forceinline__ void mma16816(float* d, const uint32_t* a, const uint32_t* b) {
    asm volatile("mma.sync.aligned.m16n8k16.row.col.f32.bf16.bf16.f32 "
                 "{%0,%1,%2,%3}, {%4,%5,%6,%7}, {%8,%9}, {%0,%1,%2,%3};"
                 : "+f"(d[0]), "+f"(d[1]), "+f"(d[2]), "+f"(d[3])
                 : "r"(a[0]), "r"(a[1]), "r"(a[2]), "r"(a[3]), "r"(b[0]), "r"(b[1]));
}

// swizzled byte offset of (row, colbyte) in a 128-row x 256B tile
__device__ __forceinline__ uint32_t swz(int row, int colbyte) {
    return (uint32_t)(row * 256 + (colbyte ^ ((row & 7) << 4)));
}
__device__ __forceinline__ void split2(float x, float y, uint32_t& hp, uint32_t& lp) {
    __nv_bfloat16 hx = __float2bfloat16(x);
    __nv_bfloat16 hy = __float2bfloat16(y);
    __nv_bfloat16 lx = __float2bfloat16(x - __bfloat162float(hx));
    __nv_bfloat16 ly = __float2bfloat16(y - __bfloat162float(hy));
    hp = ((uint32_t)__bfloat16_as_ushort(hy) << 16) | __bfloat16_as_ushort(hx);
    lp = ((uint32_t)__bfloat16_as_ushort(ly) << 16) | __bfloat16_as_ushort(lx);
}

// ---------------- prep: zero accum + split weights + fp16 child_h ----------------
struct PrepArgs { const float* W[10]; const float* child_h; };

__global__ void prep_kernel(PrepArgs pa, int M) {
    int stride = gridDim.x * blockDim.x;
    int gt = blockIdx.x * blockDim.x + threadIdx.x;
    int n4 = M * Hd / 4;
    float4 z = make_float4(0.f, 0.f, 0.f, 0.f);
    for (int i = gt; i < n4; i += stride) {
        ((float4*)g_hhat)[i]  = z;
        ((float4*)g_sumfc)[i] = z;
    }
    for (int i = gt; i < M; i += stride) {
        g_segsum[i] = 0.f;
        g_segmax[i] = 0u;
    }
    for (int idx = gt; idx < 10 * 8192; idx += stride) {
        int w = idx >> 13;
        int i = idx & 8191;
        int row = i >> 6;
        int c2 = i & 63;
        float2 v = *(const float2*)(pa.W[w] + (size_t)row * Hd + c2 * 2);
        uint32_t hp, lp;
        split2(v.x, v.y, hp, lp);
        uint32_t off = swz(row, c2 * 4);
        *(uint32_t*)(g_Wbhi + w * 32768 + off) = hp;
        *(uint32_t*)(g_Wblo + w * 32768 + off) = lp;
    }
    // fp16 shadow of child_h
    int n2 = M * Hd / 2;
    for (int i = gt; i < n2; i += stride) {
        float2 v = ((const float2*)pa.child_h)[i];
        ((__half2*)g_chh)[i] = __floats2half2_rn(v.x, v.y);
    }
}

// ---------------- shared GEMM building blocks ----------------
#define SA_HI 0
#define SA_LO 32768
#define SW_HI 65536
#define SW_LO 98304
#define S_BIAS 131072
#define S_TOT1 (131072 + 512)

__device__ __forceinline__ void conv_tile(const float* __restrict__ A, int m0, int M,
                                          char* hi, char* lo, int tid) {
#pragma unroll
    for (int it = 0; it < 8192 / NT; it++) {
        int i = tid + it * NT;
        int row = i >> 6;
        int c2 = i & 63;
        float2 v = make_float2(0.f, 0.f);
        if (m0 + row < M) v = *(const float2*)(A + (size_t)(m0 + row) * Hd + c2 * 2);
        uint32_t hp, lp;
        split2(v.x, v.y, hp, lp);
        uint32_t off = swz(row, c2 * 4);
        *(uint32_t*)(hi + off) = hp;
        *(uint32_t*)(lo + off) = lp;
    }
}

__device__ __forceinline__ void copy_w(char* sm, const char* whi, const char* wlo, int tid) {
    const uint4* shi = (const uint4*)whi;
    const uint4* slo = (const uint4*)wlo;
#pragma unroll
    for (int it = 0; it < 2048 / NT; it++) {
        int i = tid + it * NT;
        ((uint4*)(sm + SW_HI))[i] = shi[i];
        ((uint4*)(sm + SW_LO))[i] = slo[i];
    }
}

// compute 128x128 bf16x3 gemm tile into acc[2][4][4] (per-thread fragments)
__device__ __forceinline__ void gemm_core(const uint32_t smb, float acc[2][4][4],
                                          int arow0, int akb, int brow0, int bkb) {
#pragma unroll
    for (int ti = 0; ti < 2; ti++)
#pragma unroll
        for (int tj = 0; tj < 4; tj++)
#pragma unroll
            for (int k = 0; k < 4; k++) acc[ti][tj][k] = 0.f;

#pragma unroll
    for (int ks = 0; ks < 8; ks++) {
        const int kb0 = ks * 32;
        uint32_t ah[2][4], al[2][4], bh[2][4], bl[2][4];
#pragma unroll
        for (int ti = 0; ti < 2; ti++) {
            int row = arow0 + ti * 16;
            uint32_t off = swz(row, kb0 + akb);
            ldm4(ah[ti], smb + SA_HI + off);
            ldm4(al[ti], smb + SA_LO + off);
        }
#pragma unroll
        for (int tp = 0; tp < 2; tp++) {
            int row = brow0 + tp * 16;
            uint32_t off = swz(row, kb0 + bkb);
            ldm4(bh[tp], smb + SW_HI + off);
            ldm4(bl[tp], smb + SW_LO + off);
        }
#pragma unroll
        for (int ti = 0; ti < 2; ti++)
#pragma unroll
            for (int tj = 0; tj < 4; tj++) {
                const uint32_t* bhp = &bh[tj >> 1][(tj & 1) * 2];
                const uint32_t* blp = &bl[tj >> 1][(tj & 1) * 2];
                mma16816(acc[ti][tj], ah[ti], bhp);
                mma16816(acc[ti][tj], ah[ti], blp);
                mma16816(acc[ti][tj], al[ti], bhp);
            }
    }
}

// ---------------- batched GEMM: fp32 or fp16 outputs per slot ----------------
struct TcArgs {
    const float* A1;
    const float* A2;
    const char* whi[7];
    const char* wlo[7];
    const float* b[7];
    float* C[7];      // fp32 output (or null)
    __half* Ch[7];    // fp16 output (takes precedence if non-null)
    int nW1, nW2, M;
};

__global__ void __launch_bounds__(NT, 1) gemm_mma(TcArgs ga) {
    extern __shared__ char sm[];
    const uint32_t smb = smem_u32(sm);
    const int tid = threadIdx.x;
    const int wid = tid >> 5;
    const int lane = tid & 31;
    const int m0 = blockIdx.x * 128;
    const int M = ga.M;
    const int wm = wid >> 2;
    const int wn = wid & 3;
    const int sub = lane & 7;
    const int quad = lane >> 3;
    const int arow0 = wm * 32 + sub + (quad & 1) * 8;
    const int akb   = (quad >> 1) * 16;
    const int brow0 = wn * 32 + sub + (quad >> 1) * 8;
    const int bkb   = (quad & 1) * 16;

    const float* Acur = ga.A1;
    int nW = ga.nW1;
    int wbase = 0;

    for (int sec = 0; sec < 2; sec++) {
        if (nW == 0) break;
        __syncthreads();
        conv_tile(Acur, m0, M, sm + SA_HI, sm + SA_LO, tid);

        for (int wi = 0; wi < nW; wi++) {
            const int w = wbase + wi;
            __syncthreads();
            copy_w(sm, ga.whi[w], ga.wlo[w], tid);
            if (tid < 128) ((float*)(sm + S_BIAS))[tid] = ga.b[w] ? __ldg(ga.b[w] + tid) : 0.f;
            __syncthreads();

            float acc[2][4][4];
            gemm_core(smb, acc, arow0, akb, brow0, bkb);

            const int g = lane >> 2;
            const int tg = lane & 3;
            float* __restrict__ C = ga.C[w];
            __half* __restrict__ Ch = ga.Ch[w];
            const float* sb = (const float*)(sm + S_BIAS);
#pragma unroll
            for (int ti = 0; ti < 2; ti++)
#pragma unroll
                for (int tj = 0; tj < 4; tj++) {
                    int row = m0 + wm * 32 + ti * 16 + g;
                    int col = wn * 32 + tj * 8 + tg * 2;
                    float2 bv = *(const float2*)(sb + col);
                    if (Ch) {
                        if (row < M)
                            *(__half2*)(Ch + (size_t)row * Hd + col) =
                                __floats2half2_rn(acc[ti][tj][0] + bv.x, acc[ti][tj][1] + bv.y);
                        if (row + 8 < M)
                            *(__half2*)(Ch + (size_t)(row + 8) * Hd + col) =
                                __floats2half2_rn(acc[ti][tj][2] + bv.x, acc[ti][tj][3] + bv.y);
                    } else {
                        if (row < M)
                            *(float2*)(C + (size_t)row * Hd + col) =
                                make_float2(acc[ti][tj][0] + bv.x, acc[ti][tj][1] + bv.y);
                        if (row + 8 < M)
                            *(float2*)(C + (size_t)(row + 8) * Hd + col) =
                                make_float2(acc[ti][tj][2] + bv.x, acc[ti][tj][3] + bv.y);
                    }
                }
        }
        wbase += nW;
        Acur = ga.A2;
        nW = ga.nW2;
    }
}

// ---------------- pair pass 1: e = tanh(Ah[chi]+Bx[ci]) . v ; segmax ----------------
__global__ void pair_e_kernel(const int* __restrict__ ci, const int* __restrict__ chi,
                              const float* __restrict__ v, int L) {
    __shared__ float vs[Hd];
    if (threadIdx.x < Hd) vs[threadIdx.x] = v[threadIdx.x];
    __syncthreads();

    int w = blockIdx.x * (blockDim.x >> 5) + (threadIdx.x >> 5);
    int lane = threadIdx.x & 31;
    if (w >= L) return;

    int c  = __ldg(ci + w);
    int ch = __ldg(chi + w);
    float4 a  = ld_half4(g_Ahh + (size_t)ch * Hd + lane * 4);
    float4 b  = ld_half4(g_Bxh + (size_t)c * Hd + lane * 4);
    float4 vv = *(const float4*)(vs + lane * 4);

    float s = tanh_f(a.x + b.x) * vv.x + tanh_f(a.y + b.y) * vv.y +
              tanh_f(a.z + b.z) * vv.z + tanh_f(a.w + b.w) * vv.w;
#pragma unroll
    for (int o = 16; o; o >>= 1) s += __shfl_xor_sync(0xFFFFFFFFu, s, o);

    if (lane == 0) {
        g_e[w] = s;
        atomicMax(g_segmax + c, encf(s));
    }
}

// ---------------- pair pass 2: xexp = exp(e - segmax[ci]); segsum ----------------
__global__ void pair_exp_kernel(const int* __restrict__ ci, int L) {
    int l = blockIdx.x * blockDim.x + threadIdx.x;
    if (l >= L) return;
    int c = ci[l];
    float mx = decf(g_segmax[c]);
    float xe = __expf(g_e[l] - mx);
    g_e[l] = xe;
    atomicAdd(g_segsum + c, xe);
}

// ---------------- pair pass 3: h_hat and sum_f_c accumulation ----------------
__global__ void pair_acc_kernel(const float* __restrict__ child_c,
                                const int* __restrict__ ci, const int* __restrict__ chi,
                                int L) {
    int w = blockIdx.x * (blockDim.x >> 5) + (threadIdx.x >> 5);
    int lane = threadIdx.x & 31;
    if (w >= L) return;

    int c  = __ldg(ci + w);
    int ch = __ldg(chi + w);
    float attn = __ldg(g_e + w) / (__ldg(g_segsum + c) + SEPS);

    size_t co  = (size_t)c * Hd + lane * 4;
    size_t cho = (size_t)ch * Hd + lane * 4;

    float4 hv = ld_half4(g_chh + cho);
    red4(g_hhat + co, attn * hv.x, attn * hv.y, attn * hv.z, attn * hv.w);

    float4 wf = ld_half4(g_Wfxh + co);
    float4 uf = ld_half4(g_Ufhh + cho);
    float4 cv = *(const float4*)(child_c + cho);
    float fx = sigm_f(wf.x + uf.x) * cv.x;
    float fy = sigm_f(wf.y + uf.y) * cv.y;
    float fz = sigm_f(wf.z + uf.z) * cv.z;
    float fw = sigm_f(wf.w + uf.w) * cv.w;
    red4(g_sumfc + co, fx, fy, fz, fw);
}

// ---------------- epilogue: gates -> h, c ----------------
__global__ void epilogue_kernel(float* __restrict__ outh, float* __restrict__ outc, int n4) {
    int stride = gridDim.x * blockDim.x;
    for (int i = blockIdx.x * blockDim.x + threadIdx.x; i < n4; i += stride) {
        float4 wix = ((const float4*)g_Wix)[i];
        float4 uih = ((const float4*)g_Uih)[i];
        float4 wcx = ((const float4*)g_Wcx)[i];
        float4 uch = ((const float4*)g_Uch)[i];
        float4 wox = ((const float4*)g_Wox)[i];
        float4 uoh = ((const float4*)g_Uoh)[i];
        float4 sf  = ((const float4*)g_sumfc)[i];

        float4 hc, cc;
        {
            float ig = sigm_f(wix.x + uih.x);
            float ct = tanh_f(wcx.x + uch.x);
            float cval = fmaf(ig, ct, sf.x);
            float og = sigm_f(wox.x + uoh.x);
            cc.x = cval; hc.x = og * tanh_f(cval);
        }
        {
            float ig = sigm_f(wix.y + uih.y);
            float ct = tanh_f(wcx.y + uch.y);
            float cval = fmaf(ig, ct, sf.y);
            float og = sigm_f(wox.y + uoh.y);
            cc.y = cval; hc.y = og * tanh_f(cval);
        }
        {
            float ig = sigm_f(wix.z + uih.z);
            float ct = tanh_f(wcx.z + uch.z);
            float cval = fmaf(ig, ct, sf.z);
            float og = sigm_f(wox.z + uoh.z);
            cc.z = cval; hc.z = og * tanh_f(cval);
        }
        {
            float ig = sigm_f(wix.w + uih.w);
            float ct = tanh_f(wcx.w + uch.w);
            float cval = fmaf(ig, ct, sf.w);
            float og = sigm_f(wox.w + uoh.w);
            cc.w = cval; hc.w = og * tanh_f(cval);
        }
        ((float4*)outh)[i] = hc;
        ((float4*)outc)[i] = cc;
    }
}

// ---------------- launch ----------------
extern "C" void kernel_launch(void* const* d_in, const int* in_sizes, int n_in,
                              void* d_out, int out_size) {
    const float* x_emb   = (const float*)d_in[0];
    const float* child_h = (const float*)d_in[1];
    const float* child_c = (const float*)d_in[2];
    const int*   ci      = (const int*)d_in[3];
    const int*   chi     = (const int*)d_in[4];
    const float* Wi_w = (const float*)d_in[5];
    const float* Ui_w = (const float*)d_in[6];
    const float* Wf_w = (const float*)d_in[7];
    const float* Uf_w = (const float*)d_in[8];
    const float* Wo_w = (const float*)d_in[9];
    const float* Uo_w = (const float*)d_in[10];
    const float* Wc_w = (const float*)d_in[11];
    const float* Uc_w = (const float*)d_in[12];
    const float* Wa_w = (const float*)d_in[13];
    const float* Ua_w = (const float*)d_in[14];
    const float* Wi_b = (const float*)d_in[15];
    const float* Wf_b = (const float*)d_in[16];
    const float* Wo_b = (const float*)d_in[17];
    const float* Wc_b = (const float*)d_in[18];
    const float* Wa_b = (const float*)d_in[19];
    const float* v_w  = (const float*)d_in[20];

    const int M = in_sizes[0] / Hd;
    const int L = in_sizes[3];

    float *p_Wix, *p_Wox, *p_Wcx, *p_hhat, *p_Uih, *p_Uch, *p_Uoh;
    cudaGetSymbolAddress((void**)&p_Wix, g_Wix);
    cudaGetSymbolAddress((void**)&p_Wox, g_Wox);
    cudaGetSymbolAddress((void**)&p_Wcx, g_Wcx);
    cudaGetSymbolAddress((void**)&p_hhat, g_hhat);
    cudaGetSymbolAddress((void**)&p_Uih, g_Uih);
    cudaGetSymbolAddress((void**)&p_Uch, g_Uch);
    cudaGetSymbolAddress((void**)&p_Uoh, g_Uoh);
    __half *p_Ahh, *p_Bxh, *p_Wfxh, *p_Ufhh;
    cudaGetSymbolAddress((void**)&p_Ahh,  g_Ahh);
    cudaGetSymbolAddress((void**)&p_Bxh,  g_Bxh);
    cudaGetSymbolAddress((void**)&p_Wfxh, g_Wfxh);
    cudaGetSymbolAddress((void**)&p_Ufhh, g_Ufhh);
    char *p_whi, *p_wlo;
    cudaGetSymbolAddress((void**)&p_whi, g_Wbhi);
    cudaGetSymbolAddress((void**)&p_wlo, g_Wblo);

    float* outh = (float*)d_out;
    float* outc = outh + (size_t)M * Hd;

    const int mtiles = (M + 127) / 128;

    cudaFuncSetAttribute(gemm_mma, cudaFuncAttributeMaxDynamicSharedMemorySize, S_TOT1);

    // weight order in g_Wb: 0:Ua 1:Wi 2:Wf 3:Wo 4:Wc 5:Wa 6:Uf 7:Ui 8:Uc 9:Uo
    {
        PrepArgs pa;
        pa.W[0] = Ua_w; pa.W[1] = Wi_w; pa.W[2] = Wf_w; pa.W[3] = Wo_w; pa.W[4] = Wc_w;
        pa.W[5] = Wa_w; pa.W[6] = Uf_w; pa.W[7] = Ui_w; pa.W[8] = Uc_w; pa.W[9] = Uo_w;
        pa.child_h = child_h;
        prep_kernel<<<296, 256>>>(pa, M);
    }

    // phase 1: x-side (Bx, Wix, Wfx, Wox, Wcx) + child_h-side (Ah, Ufh)
    // fp16 outputs: Bx, Wfx, Ah, Ufh (pair-kernel-only consumers)
    {
        TcArgs ga;
        ga.A1 = x_emb; ga.A2 = child_h; ga.nW1 = 5; ga.nW2 = 2; ga.M = M;
        int slot[7] = {0, 1, 2, 3, 4, 5, 6};
        const float* bs[7] = {nullptr, Wi_b, Wf_b, Wo_b, Wc_b, Wa_b, nullptr};
        float* cs[7]  = {nullptr, p_Wix, nullptr, p_Wox, p_Wcx, nullptr, nullptr};
        __half* chs[7] = {p_Bxh, nullptr, p_Wfxh, nullptr, nullptr, p_Ahh, p_Ufhh};
        for (int i = 0; i < 7; i++) {
            ga.whi[i] = p_whi + slot[i] * 32768;
            ga.wlo[i] = p_wlo + slot[i] * 32768;
            ga.b[i] = bs[i];
            ga.C[i] = cs[i];
            ga.Ch[i] = chs[i];
        }
        gemm_mma<<<mtiles, NT, S_TOT1>>>(ga);
    }

    // attention + forget-gate pair passes
    pair_e_kernel<<<(L + 7) / 8, 256>>>(ci, chi, v_w, L);
    pair_exp_kernel<<<(L + 255) / 256, 256>>>(ci, L);
    pair_acc_kernel<<<(L + 7) / 8, 256>>>(child_c, ci, chi, L);

    // phase 3: h_hat-side (Uih, Uch, Uoh), fp32 outputs
    {
        TcArgs ga;
        ga.A1 = p_hhat; ga.A2 = nullptr; ga.nW1 = 3; ga.nW2 = 0; ga.M = M;
        int slot[7] = {7, 8, 9, 7, 7, 7, 7};
        float* cs[7] = {p_Uih, p_Uch, p_Uoh, p_Uih, p_Uih, p_Uih, p_Uih};
        for (int i = 0; i < 7; i++) {
            ga.whi[i] = p_whi + slot[i] * 32768;
            ga.wlo[i] = p_wlo + slot[i] * 32768;
            ga.b[i] = nullptr;
            ga.C[i] = cs[i];
            ga.Ch[i] = nullptr;
        }
        gemm_mma<<<mtiles, NT, S_TOT1>>>(ga);
    }

    const int n4 = M * Hd / 4;
    epilogue_kernel<<<(n4 + 255) / 256, 256>>>(outh, outc, n4);
}

// round 11
// speedup vs baseline: 1.1706x; 1.0838x over previous
#include <cuda_runtime.h>
#include <cuda_fp16.h>
#include <cstdint>

#define Hd 128
#define MAXM 50048
#define MAXL 400128
#define SEPS 1e-9f
#define NT 512

// ---------------- scratch (device globals; no allocations) ----------------
__device__ float g_hhat[MAXM*Hd];
__device__ float g_sumfc[MAXM*Hd];
// fp16 GEMM outputs / pair operands
__device__ __half g_Ahh [MAXM*Hd];
__device__ __half g_Bxh [MAXM*Hd];
__device__ __half g_Wfxh[MAXM*Hd];
__device__ __half g_Ufhh[MAXM*Hd];
__device__ __half g_Wixh[MAXM*Hd];
__device__ __half g_Woxh[MAXM*Hd];
__device__ __half g_Wcxh[MAXM*Hd];
__device__ __half g_Uihh[MAXM*Hd];
__device__ __half g_Uchh[MAXM*Hd];
__device__ __half g_Uohh[MAXM*Hd];
__device__ __half g_chh [MAXM*Hd];   // fp16 shadow of child_h
__device__ __half g_cch [MAXM*Hd];   // fp16 shadow of child_c
__device__ float g_e[MAXL];
__device__ float g_segsum[MAXM];
__device__ unsigned g_segmax[MAXM];
// pre-swizzled single-fp16 weights: 10 x 128x128, 32KB each
__device__ __align__(16) char g_Wbh[10 * 32768];

// ---------------- scalar helpers ----------------
__device__ __forceinline__ float sigm_f(float x) {
    return __fdividef(1.0f, 1.0f + __expf(-x));
}
__device__ __forceinline__ float tanh_f(float x) {
    float e2 = __expf(2.0f * x);
    return 1.0f - __fdividef(2.0f, e2 + 1.0f);
}
__device__ __forceinline__ unsigned encf(float f) {
    unsigned b = __float_as_uint(f);
    return (b & 0x80000000u) ? ~b : (b | 0x80000000u);
}
__device__ __forceinline__ float decf(unsigned u) {
    return (u & 0x80000000u) ? __uint_as_float(u ^ 0x80000000u) : __uint_as_float(~u);
}
__device__ __forceinline__ void red4(float* p, float x, float y, float z, float w) {
    asm volatile("red.global.add.v4.f32 [%0], {%1, %2, %3, %4};"
                 :: "l"(p), "f"(x), "f"(y), "f"(z), "f"(w) : "memory");
}
__device__ __forceinline__ uint32_t smem_u32(const void* p) {
    uint32_t a;
    asm("{ .reg .u64 t; cvta.to.shared.u64 t, %1; cvt.u32.u64 %0, t; }" : "=r"(a) : "l"(p));
    return a;
}
__device__ __forceinline__ float4 ld_half4(const __half* p) {
    uint2 v = *(const uint2*)p;
    float2 lo = __half22float2(*(__half2*)&v.x);
    float2 hi = __half22float2(*(__half2*)&v.y);
    return make_float4(lo.x, lo.y, hi.x, hi.y);
}
__device__ __forceinline__ uint32_t packh2(float x, float y) {
    __half2 h = __floats2half2_rn(x, y);
    return *(uint32_t*)&h;
}

// ---------------- mma / ldmatrix wrappers ----------------
__device__ __forceinline__ void ldm4(uint32_t* r, uint32_t addr) {
    asm volatile("ldmatrix.sync.aligned.m8n8.x4.shared.b16 {%0,%1,%2,%3}, [%4];"
                 : "=r"(r[0]), "=r"(r[1]), "=r"(r[2]), "=r"(r[3]) : "r"(addr));
}
__device__ __forceinline__ void mma16816h(float* d, const uint32_t* a, const uint32_t* b) {
    asm volatile("mma.sync.aligned.m16n8k16.row.col.f32.f16.f16.f32 "
                 "{%0,%1,%2,%3}, {%4,%5,%6,%7}, {%8,%9}, {%0,%1,%2,%3};"
                 : "+f"(d[0]), "+f"(d[1]), "+f"(d[2]), "+f"(d[3])
                 : "r"(a[0]), "r"(a[1]), "r"(a[2]), "r"(a[3]), "r"(b[0]), "r"(b[1]));
}

// swizzled byte offset of (row, colbyte) in a 128-row x 256B tile
__device__ __forceinline__ uint32_t swz(int row, int colbyte) {
    return (uint32_t)(row * 256 + (colbyte ^ ((row & 7) << 4)));
}
// fp16 hi/lo split of two floats
__device__ __forceinline__ void split2h(float x, float y, uint32_t& hp, uint32_t& lp) {
    __half hx = __float2half_rn(x);
    __half hy = __float2half_rn(y);
    __half lx = __float2half_rn(x - __half2float(hx));
    __half ly = __float2half_rn(y - __half2float(hy));
    hp = ((uint32_t)__half_as_ushort(hy) << 16) | __half_as_ushort(hx);
    lp = ((uint32_t)__half_as_ushort(ly) << 16) | __half_as_ushort(lx);
}

// ---------------- prep: zero accum + fp16 weights + fp16 shadows ----------------
struct PrepArgs { const float* W[10]; const float* child_h; const float* child_c; };

__global__ void prep_kernel(PrepArgs pa, int M) {
    int stride = gridDim.x * blockDim.x;
    int gt = blockIdx.x * blockDim.x + threadIdx.x;
    int n4 = M * Hd / 4;
    float4 z = make_float4(0.f, 0.f, 0.f, 0.f);
    for (int i = gt; i < n4; i += stride) {
        ((float4*)g_hhat)[i]  = z;
        ((float4*)g_sumfc)[i] = z;
    }
    for (int i = gt; i < M; i += stride) {
        g_segsum[i] = 0.f;
        g_segmax[i] = 0u;
    }
    // weights -> single fp16, pre-swizzled
    for (int idx = gt; idx < 10 * 8192; idx += stride) {
        int w = idx >> 13;
        int i = idx & 8191;
        int row = i >> 6;
        int c2 = i & 63;
        float2 v = *(const float2*)(pa.W[w] + (size_t)row * Hd + c2 * 2);
        *(uint32_t*)(g_Wbh + w * 32768 + swz(row, c2 * 4)) = packh2(v.x, v.y);
    }
    // fp16 shadows of child_h, child_c
    int n2 = M * Hd / 2;
    for (int i = gt; i < n2; i += stride) {
        float2 vh = ((const float2*)pa.child_h)[i];
        float2 vc = ((const float2*)pa.child_c)[i];
        ((__half2*)g_chh)[i] = __floats2half2_rn(vh.x, vh.y);
        ((__half2*)g_cch)[i] = __floats2half2_rn(vc.x, vc.y);
    }
}

// ---------------- shared GEMM building blocks ----------------
#define SA_HI 0
#define SA_LO 32768
#define SW    65536
#define S_BIAS 98304
#define S_TOT1 (98304 + 512)

__device__ __forceinline__ void conv_tile(const float* __restrict__ A, int m0, int M,
                                          char* hi, char* lo, int tid) {
#pragma unroll
    for (int it = 0; it < 8192 / NT; it++) {
        int i = tid + it * NT;
        int row = i >> 6;
        int c2 = i & 63;
        float2 v = make_float2(0.f, 0.f);
        if (m0 + row < M) v = *(const float2*)(A + (size_t)(m0 + row) * Hd + c2 * 2);
        uint32_t hp, lp;
        split2h(v.x, v.y, hp, lp);
        uint32_t off = swz(row, c2 * 4);
        *(uint32_t*)(hi + off) = hp;
        *(uint32_t*)(lo + off) = lp;
    }
}

__device__ __forceinline__ void copy_w(char* sm, const char* wh, int tid) {
    const uint4* s = (const uint4*)wh;
#pragma unroll
    for (int it = 0; it < 2048 / NT; it++) {
        int i = tid + it * NT;
        ((uint4*)(sm + SW))[i] = s[i];
    }
}

// compute 128x128 fp16x2 gemm tile into acc[2][4][4]
__device__ __forceinline__ void gemm_core(const uint32_t smb, float acc[2][4][4],
                                          int arow0, int akb, int brow0, int bkb) {
#pragma unroll
    for (int ti = 0; ti < 2; ti++)
#pragma unroll
        for (int tj = 0; tj < 4; tj++)
#pragma unroll
            for (int k = 0; k < 4; k++) acc[ti][tj][k] = 0.f;

#pragma unroll
    for (int ks = 0; ks < 8; ks++) {
        const int kb0 = ks * 32;
        uint32_t ah[2][4], al[2][4], bh[2][4];
#pragma unroll
        for (int ti = 0; ti < 2; ti++) {
            int row = arow0 + ti * 16;
            uint32_t off = swz(row, kb0 + akb);
            ldm4(ah[ti], smb + SA_HI + off);
            ldm4(al[ti], smb + SA_LO + off);
        }
#pragma unroll
        for (int tp = 0; tp < 2; tp++) {
            int row = brow0 + tp * 16;
            ldm4(bh[tp], smb + SW + swz(row, kb0 + bkb));
        }
#pragma unroll
        for (int ti = 0; ti < 2; ti++)
#pragma unroll
            for (int tj = 0; tj < 4; tj++) {
                const uint32_t* bp = &bh[tj >> 1][(tj & 1) * 2];
                mma16816h(acc[ti][tj], ah[ti], bp);   // hi * w
                mma16816h(acc[ti][tj], al[ti], bp);   // lo * w
            }
    }
}

// ---------------- batched GEMM: fp16 outputs ----------------
struct TcArgs {
    const float* A1;
    const float* A2;
    const char* wh[7];
    const float* b[7];
    __half* C[7];
    int nW1, nW2, M;
};

__global__ void __launch_bounds__(NT, 1) gemm_mma(TcArgs ga) {
    extern __shared__ char sm[];
    const uint32_t smb = smem_u32(sm);
    const int tid = threadIdx.x;
    const int wid = tid >> 5;
    const int lane = tid & 31;
    const int m0 = blockIdx.x * 128;
    const int M = ga.M;
    const int wm = wid >> 2;
    const int wn = wid & 3;
    const int sub = lane & 7;
    const int quad = lane >> 3;
    const int arow0 = wm * 32 + sub + (quad & 1) * 8;
    const int akb   = (quad >> 1) * 16;
    const int brow0 = wn * 32 + sub + (quad >> 1) * 8;
    const int bkb   = (quad & 1) * 16;

    const float* Acur = ga.A1;
    int nW = ga.nW1;
    int wbase = 0;

    for (int sec = 0; sec < 2; sec++) {
        if (nW == 0) break;
        __syncthreads();
        conv_tile(Acur, m0, M, sm + SA_HI, sm + SA_LO, tid);

        for (int wi = 0; wi < nW; wi++) {
            const int w = wbase + wi;
            __syncthreads();
            copy_w(sm, ga.wh[w], tid);
            if (tid < 128) ((float*)(sm + S_BIAS))[tid] = ga.b[w] ? __ldg(ga.b[w] + tid) : 0.f;
            __syncthreads();

            float acc[2][4][4];
            gemm_core(smb, acc, arow0, akb, brow0, bkb);

            const int g = lane >> 2;
            const int tg = lane & 3;
            __half* __restrict__ C = ga.C[w];
            const float* sb = (const float*)(sm + S_BIAS);
#pragma unroll
            for (int ti = 0; ti < 2; ti++)
#pragma unroll
                for (int tj = 0; tj < 4; tj++) {
                    int row = m0 + wm * 32 + ti * 16 + g;
                    int col = wn * 32 + tj * 8 + tg * 2;
                    float2 bv = *(const float2*)(sb + col);
                    if (row < M)
                        *(__half2*)(C + (size_t)row * Hd + col) =
                            __floats2half2_rn(acc[ti][tj][0] + bv.x, acc[ti][tj][1] + bv.y);
                    if (row + 8 < M)
                        *(__half2*)(C + (size_t)(row + 8) * Hd + col) =
                            __floats2half2_rn(acc[ti][tj][2] + bv.x, acc[ti][tj][3] + bv.y);
                }
        }
        wbase += nW;
        Acur = ga.A2;
        nW = ga.nW2;
    }
}

// ---------------- pair pass 1: e = tanh(Ah[chi]+Bx[ci]) . v ; segmax ----------------
__global__ void pair_e_kernel(const int* __restrict__ ci, const int* __restrict__ chi,
                              const float* __restrict__ v, int L) {
    __shared__ float vs[Hd];
    if (threadIdx.x < Hd) vs[threadIdx.x] = v[threadIdx.x];
    __syncthreads();

    int w = blockIdx.x * (blockDim.x >> 5) + (threadIdx.x >> 5);
    int lane = threadIdx.x & 31;
    if (w >= L) return;

    int c  = __ldg(ci + w);
    int ch = __ldg(chi + w);
    float4 a  = ld_half4(g_Ahh + (size_t)ch * Hd + lane * 4);
    float4 b  = ld_half4(g_Bxh + (size_t)c * Hd + lane * 4);
    float4 vv = *(const float4*)(vs + lane * 4);

    float s = tanh_f(a.x + b.x) * vv.x + tanh_f(a.y + b.y) * vv.y +
              tanh_f(a.z + b.z) * vv.z + tanh_f(a.w + b.w) * vv.w;
#pragma unroll
    for (int o = 16; o; o >>= 1) s += __shfl_xor_sync(0xFFFFFFFFu, s, o);

    if (lane == 0) {
        g_e[w] = s;
        atomicMax(g_segmax + c, encf(s));
    }
}

// ---------------- pair pass 2: xexp = exp(e - segmax[ci]); segsum ----------------
__global__ void pair_exp_kernel(const int* __restrict__ ci, int L) {
    int l = blockIdx.x * blockDim.x + threadIdx.x;
    if (l >= L) return;
    int c = ci[l];
    float mx = decf(g_segmax[c]);
    float xe = __expf(g_e[l] - mx);
    g_e[l] = xe;
    atomicAdd(g_segsum + c, xe);
}

// ---------------- pair pass 3: h_hat and sum_f_c accumulation ----------------
__global__ void pair_acc_kernel(const int* __restrict__ ci, const int* __restrict__ chi,
                                int L) {
    int w = blockIdx.x * (blockDim.x >> 5) + (threadIdx.x >> 5);
    int lane = threadIdx.x & 31;
    if (w >= L) return;

    int c  = __ldg(ci + w);
    int ch = __ldg(chi + w);
    float attn = __ldg(g_e + w) / (__ldg(g_segsum + c) + SEPS);

    size_t co  = (size_t)c * Hd + lane * 4;
    size_t cho = (size_t)ch * Hd + lane * 4;

    float4 hv = ld_half4(g_chh + cho);
    red4(g_hhat + co, attn * hv.x, attn * hv.y, attn * hv.z, attn * hv.w);

    float4 wf = ld_half4(g_Wfxh + co);
    float4 uf = ld_half4(g_Ufhh + cho);
    float4 cv = ld_half4(g_cch + cho);
    float fx = sigm_f(wf.x + uf.x) * cv.x;
    float fy = sigm_f(wf.y + uf.y) * cv.y;
    float fz = sigm_f(wf.z + uf.z) * cv.z;
    float fw = sigm_f(wf.w + uf.w) * cv.w;
    red4(g_sumfc + co, fx, fy, fz, fw);
}

// ---------------- epilogue: gates -> h, c ----------------
__global__ void epilogue_kernel(float* __restrict__ outh, float* __restrict__ outc, int n4) {
    int stride = gridDim.x * blockDim.x;
    for (int i = blockIdx.x * blockDim.x + threadIdx.x; i < n4; i += stride) {
        size_t e = (size_t)i * 4;
        float4 wix = ld_half4(g_Wixh + e);
        float4 uih = ld_half4(g_Uihh + e);
        float4 wcx = ld_half4(g_Wcxh + e);
        float4 uch = ld_half4(g_Uchh + e);
        float4 wox = ld_half4(g_Woxh + e);
        float4 uoh = ld_half4(g_Uohh + e);
        float4 sf  = ((const float4*)g_sumfc)[i];

        float4 hc, cc;
        {
            float ig = sigm_f(wix.x + uih.x);
            float ct = tanh_f(wcx.x + uch.x);
            float cval = fmaf(ig, ct, sf.x);
            float og = sigm_f(wox.x + uoh.x);
            cc.x = cval; hc.x = og * tanh_f(cval);
        }
        {
            float ig = sigm_f(wix.y + uih.y);
            float ct = tanh_f(wcx.y + uch.y);
            float cval = fmaf(ig, ct, sf.y);
            float og = sigm_f(wox.y + uoh.y);
            cc.y = cval; hc.y = og * tanh_f(cval);
        }
        {
            float ig = sigm_f(wix.z + uih.z);
            float ct = tanh_f(wcx.z + uch.z);
            float cval = fmaf(ig, ct, sf.z);
            float og = sigm_f(wox.z + uoh.z);
            cc.z = cval; hc.z = og * tanh_f(cval);
        }
        {
            float ig = sigm_f(wix.w + uih.w);
            float ct = tanh_f(wcx.w + uch.w);
            float cval = fmaf(ig, ct, sf.w);
            float og = sigm_f(wox.w + uoh.w);
            cc.w = cval; hc.w = og * tanh_f(cval);
        }
        ((float4*)outh)[i] = hc;
        ((float4*)outc)[i] = cc;
    }
}

// ---------------- launch ----------------
extern "C" void kernel_launch(void* const* d_in, const int* in_sizes, int n_in,
                              void* d_out, int out_size) {
    const float* x_emb   = (const float*)d_in[0];
    const float* child_h = (const float*)d_in[1];
    const float* child_c = (const float*)d_in[2];
    const int*   ci      = (const int*)d_in[3];
    const int*   chi     = (const int*)d_in[4];
    const float* Wi_w = (const float*)d_in[5];
    const float* Ui_w = (const float*)d_in[6];
    const float* Wf_w = (const float*)d_in[7];
    const float* Uf_w = (const float*)d_in[8];
    const float* Wo_w = (const float*)d_in[9];
    const float* Uo_w = (const float*)d_in[10];
    const float* Wc_w = (const float*)d_in[11];
    const float* Uc_w = (const float*)d_in[12];
    const float* Wa_w = (const float*)d_in[13];
    const float* Ua_w = (const float*)d_in[14];
    const float* Wi_b = (const float*)d_in[15];
    const float* Wf_b = (const float*)d_in[16];
    const float* Wo_b = (const float*)d_in[17];
    const float* Wc_b = (const float*)d_in[18];
    const float* Wa_b = (const float*)d_in[19];
    const float* v_w  = (const float*)d_in[20];

    const int M = in_sizes[0] / Hd;
    const int L = in_sizes[3];

    float *p_hhat;
    cudaGetSymbolAddress((void**)&p_hhat, g_hhat);
    __half *p_Ahh, *p_Bxh, *p_Wfxh, *p_Ufhh, *p_Wixh, *p_Woxh, *p_Wcxh, *p_Uihh, *p_Uchh, *p_Uohh;
    cudaGetSymbolAddress((void**)&p_Ahh,  g_Ahh);
    cudaGetSymbolAddress((void**)&p_Bxh,  g_Bxh);
    cudaGetSymbolAddress((void**)&p_Wfxh, g_Wfxh);
    cudaGetSymbolAddress((void**)&p_Ufhh, g_Ufhh);
    cudaGetSymbolAddress((void**)&p_Wixh, g_Wixh);
    cudaGetSymbolAddress((void**)&p_Woxh, g_Woxh);
    cudaGetSymbolAddress((void**)&p_Wcxh, g_Wcxh);
    cudaGetSymbolAddress((void**)&p_Uihh, g_Uihh);
    cudaGetSymbolAddress((void**)&p_Uchh, g_Uchh);
    cudaGetSymbolAddress((void**)&p_Uohh, g_Uohh);
    char *p_wh;
    cudaGetSymbolAddress((void**)&p_wh, g_Wbh);

    float* outh = (float*)d_out;
    float* outc = outh + (size_t)M * Hd;

    const int mtiles = (M + 127) / 128;

    cudaFuncSetAttribute(gemm_mma, cudaFuncAttributeMaxDynamicSharedMemorySize, S_TOT1);

    // weight order in g_Wbh: 0:Ua 1:Wi 2:Wf 3:Wo 4:Wc 5:Wa 6:Uf 7:Ui 8:Uc 9:Uo
    {
        PrepArgs pa;
        pa.W[0] = Ua_w; pa.W[1] = Wi_w; pa.W[2] = Wf_w; pa.W[3] = Wo_w; pa.W[4] = Wc_w;
        pa.W[5] = Wa_w; pa.W[6] = Uf_w; pa.W[7] = Ui_w; pa.W[8] = Uc_w; pa.W[9] = Uo_w;
        pa.child_h = child_h;
        pa.child_c = child_c;
        prep_kernel<<<296, 256>>>(pa, M);
    }

    // phase 1: x-side (Bx, Wix, Wfx, Wox, Wcx) + child_h-side (Ah, Ufh), all fp16 out
    {
        TcArgs ga;
        ga.A1 = x_emb; ga.A2 = child_h; ga.nW1 = 5; ga.nW2 = 2; ga.M = M;
        int slot[7] = {0, 1, 2, 3, 4, 5, 6};
        const float* bs[7] = {nullptr, Wi_b, Wf_b, Wo_b, Wc_b, Wa_b, nullptr};
        __half* cs[7] = {p_Bxh, p_Wixh, p_Wfxh, p_Woxh, p_Wcxh, p_Ahh, p_Ufhh};
        for (int i = 0; i < 7; i++) {
            ga.wh[i] = p_wh + slot[i] * 32768;
            ga.b[i] = bs[i];
            ga.C[i] = cs[i];
        }
        gemm_mma<<<mtiles, NT, S_TOT1>>>(ga);
    }

    // attention + forget-gate pair passes
    pair_e_kernel<<<(L + 7) / 8, 256>>>(ci, chi, v_w, L);
    pair_exp_kernel<<<(L + 255) / 256, 256>>>(ci, L);
    pair_acc_kernel<<<(L + 7) / 8, 256>>>(ci, chi, L);

    // phase 3: h_hat-side (Uih, Uch, Uoh), fp16 out
    {
        TcArgs ga;
        ga.A1 = p_hhat; ga.A2 = nullptr; ga.nW1 = 3; ga.nW2 = 0; ga.M = M;
        int slot[7] = {7, 8, 9, 7, 7, 7, 7};
        __half* cs[7] = {p_Uihh, p_Uchh, p_Uohh, p_Uihh, p_Uihh, p_Uihh, p_Uihh};
        for (int i = 0; i < 7; i++) {
            ga.wh[i] = p_wh + slot[i] * 32768;
            ga.b[i] = nullptr;
            ga.C[i] = cs[i];
        }
        gemm_mma<<<mtiles, NT, S_TOT1>>>(ga);
    }

    const int n4 = M * Hd / 4;
    epilogue_kernel<<<(n4 + 255) / 256, 256>>>(outh, outc, n4);
}

// round 12
// speedup vs baseline: 1.3280x; 1.1345x over previous
#include <cuda_runtime.h>
#include <cuda_fp16.h>
#include <cstdint>

#define Hd 128
#define MAXM 50048
#define MAXL 400128
#define SEPS 1e-9f
#define NT 512

// ---------------- scratch (device globals; no allocations) ----------------
__device__ float g_hhat[MAXM*Hd];
__device__ float g_sumfc[MAXM*Hd];
// fp16 GEMM outputs / pair operands
__device__ __half g_Ahh [MAXM*Hd];
__device__ __half g_Bxh [MAXM*Hd];
__device__ __half g_Wfxh[MAXM*Hd];
__device__ __half g_Ufhh[MAXM*Hd];
__device__ __half g_Wixh[MAXM*Hd];
__device__ __half g_Woxh[MAXM*Hd];
__device__ __half g_Wcxh[MAXM*Hd];
__device__ __half g_Uihh[MAXM*Hd];
__device__ __half g_Uchh[MAXM*Hd];
__device__ __half g_Uohh[MAXM*Hd];
__device__ __half g_chh [MAXM*Hd];   // fp16 shadow of child_h
__device__ __half g_cch [MAXM*Hd];   // fp16 shadow of child_c
__device__ float g_e[MAXL];
__device__ float g_segsum[MAXM];
__device__ unsigned g_segmax[MAXM];
// pre-swizzled single-fp16 weights: 10 x 128x128, 32KB each
__device__ __align__(16) char g_Wbh[10 * 32768];

// ---------------- scalar helpers ----------------
__device__ __forceinline__ float sigm_f(float x) {
    return __fdividef(1.0f, 1.0f + __expf(-x));
}
__device__ __forceinline__ float tanh_f(float x) {
    float e2 = __expf(2.0f * x);
    return 1.0f - __fdividef(2.0f, e2 + 1.0f);
}
__device__ __forceinline__ unsigned encf(float f) {
    unsigned b = __float_as_uint(f);
    return (b & 0x80000000u) ? ~b : (b | 0x80000000u);
}
__device__ __forceinline__ float decf(unsigned u) {
    return (u & 0x80000000u) ? __uint_as_float(u ^ 0x80000000u) : __uint_as_float(~u);
}
__device__ __forceinline__ void red4(float* p, float x, float y, float z, float w) {
    asm volatile("red.global.add.v4.f32 [%0], {%1, %2, %3, %4};"
                 :: "l"(p), "f"(x), "f"(y), "f"(z), "f"(w) : "memory");
}
__device__ __forceinline__ uint32_t smem_u32(const void* p) {
    uint32_t a;
    asm("{ .reg .u64 t; cvta.to.shared.u64 t, %1; cvt.u32.u64 %0, t; }" : "=r"(a) : "l"(p));
    return a;
}
__device__ __forceinline__ float4 ld_half4(const __half* p) {
    uint2 v = *(const uint2*)p;
    float2 lo = __half22float2(*(__half2*)&v.x);
    float2 hi = __half22float2(*(__half2*)&v.y);
    return make_float4(lo.x, lo.y, hi.x, hi.y);
}
__device__ __forceinline__ uint32_t packh2(float x, float y) {
    __half2 h = __floats2half2_rn(x, y);
    return *(uint32_t*)&h;
}

// ---------------- mma / ldmatrix wrappers ----------------
__device__ __forceinline__ void ldm4(uint32_t* r, uint32_t addr) {
    asm volatile("ldmatrix.sync.aligned.m8n8.x4.shared.b16 {%0,%1,%2,%3}, [%4];"
                 : "=r"(r[0]), "=r"(r[1]), "=r"(r[2]), "=r"(r[3]) : "r"(addr));
}
__device__ __forceinline__ void mma16816h(float* d, const uint32_t* a, const uint32_t* b) {
    asm volatile("mma.sync.aligned.m16n8k16.row.col.f32.f16.f16.f32 "
                 "{%0,%1,%2,%3}, {%4,%5,%6,%7}, {%8,%9}, {%0,%1,%2,%3};"
                 : "+f"(d[0]), "+f"(d[1]), "+f"(d[2]), "+f"(d[3])
                 : "r"(a[0]), "r"(a[1]), "r"(a[2]), "r"(a[3]), "r"(b[0]), "r"(b[1]));
}

// swizzled byte offset of (row, colbyte) in a 128-row x 256B tile
__device__ __forceinline__ uint32_t swz(int row, int colbyte) {
    return (uint32_t)(row * 256 + (colbyte ^ ((row & 7) << 4)));
}

// ---------------- prep: zero accum + fp16 weights + fp16 shadows ----------------
struct PrepArgs { const float* W[10]; const float* child_h; const float* child_c; };

__global__ void prep_kernel(PrepArgs pa, int M) {
    int stride = gridDim.x * blockDim.x;
    int gt = blockIdx.x * blockDim.x + threadIdx.x;
    int n4 = M * Hd / 4;
    float4 z = make_float4(0.f, 0.f, 0.f, 0.f);
    for (int i = gt; i < n4; i += stride) {
        ((float4*)g_hhat)[i]  = z;
        ((float4*)g_sumfc)[i] = z;
    }
    for (int i = gt; i < M; i += stride) {
        g_segsum[i] = 0.f;
        g_segmax[i] = 0u;
    }
    // weights -> single fp16, pre-swizzled
    for (int idx = gt; idx < 10 * 8192; idx += stride) {
        int w = idx >> 13;
        int i = idx & 8191;
        int row = i >> 6;
        int c2 = i & 63;
        float2 v = *(const float2*)(pa.W[w] + (size_t)row * Hd + c2 * 2);
        *(uint32_t*)(g_Wbh + w * 32768 + swz(row, c2 * 4)) = packh2(v.x, v.y);
    }
    // fp16 shadows of child_h, child_c
    int n2 = M * Hd / 2;
    for (int i = gt; i < n2; i += stride) {
        float2 vh = ((const float2*)pa.child_h)[i];
        float2 vc = ((const float2*)pa.child_c)[i];
        ((__half2*)g_chh)[i] = __floats2half2_rn(vh.x, vh.y);
        ((__half2*)g_cch)[i] = __floats2half2_rn(vc.x, vc.y);
    }
}

// ---------------- shared GEMM building blocks ----------------
#define SA    0
#define SW    32768
#define S_BIAS 65536
#define S_TOT1 (65536 + 512)

__device__ __forceinline__ void conv_tile(const float* __restrict__ A, int m0, int M,
                                          char* dst, int tid) {
#pragma unroll
    for (int it = 0; it < 8192 / NT; it++) {
        int i = tid + it * NT;
        int row = i >> 6;
        int c2 = i & 63;
        float2 v = make_float2(0.f, 0.f);
        if (m0 + row < M) v = *(const float2*)(A + (size_t)(m0 + row) * Hd + c2 * 2);
        *(uint32_t*)(dst + swz(row, c2 * 4)) = packh2(v.x, v.y);
    }
}

__device__ __forceinline__ void copy_w(char* sm, const char* wh, int tid) {
    const uint4* s = (const uint4*)wh;
#pragma unroll
    for (int it = 0; it < 2048 / NT; it++) {
        int i = tid + it * NT;
        ((uint4*)(sm + SW))[i] = s[i];
    }
}

// compute 128x128 fp16 gemm tile into acc[2][4][4]
__device__ __forceinline__ void gemm_core(const uint32_t smb, float acc[2][4][4],
                                          int arow0, int akb, int brow0, int bkb) {
#pragma unroll
    for (int ti = 0; ti < 2; ti++)
#pragma unroll
        for (int tj = 0; tj < 4; tj++)
#pragma unroll
            for (int k = 0; k < 4; k++) acc[ti][tj][k] = 0.f;

#pragma unroll
    for (int ks = 0; ks < 8; ks++) {
        const int kb0 = ks * 32;
        uint32_t ah[2][4], bh[2][4];
#pragma unroll
        for (int ti = 0; ti < 2; ti++) {
            int row = arow0 + ti * 16;
            ldm4(ah[ti], smb + SA + swz(row, kb0 + akb));
        }
#pragma unroll
        for (int tp = 0; tp < 2; tp++) {
            int row = brow0 + tp * 16;
            ldm4(bh[tp], smb + SW + swz(row, kb0 + bkb));
        }
#pragma unroll
        for (int ti = 0; ti < 2; ti++)
#pragma unroll
            for (int tj = 0; tj < 4; tj++) {
                const uint32_t* bp = &bh[tj >> 1][(tj & 1) * 2];
                mma16816h(acc[ti][tj], ah[ti], bp);
            }
    }
}

// ---------------- batched GEMM: fp16 outputs ----------------
struct TcArgs {
    const float* A1;
    const float* A2;
    const char* wh[7];
    const float* b[7];
    __half* C[7];
    int nW1, nW2, M;
};

__global__ void __launch_bounds__(NT, 1) gemm_mma(TcArgs ga) {
    extern __shared__ char sm[];
    const uint32_t smb = smem_u32(sm);
    const int tid = threadIdx.x;
    const int wid = tid >> 5;
    const int lane = tid & 31;
    const int m0 = blockIdx.x * 128;
    const int M = ga.M;
    const int wm = wid >> 2;
    const int wn = wid & 3;
    const int sub = lane & 7;
    const int quad = lane >> 3;
    const int arow0 = wm * 32 + sub + (quad & 1) * 8;
    const int akb   = (quad >> 1) * 16;
    const int brow0 = wn * 32 + sub + (quad >> 1) * 8;
    const int bkb   = (quad & 1) * 16;

    const float* Acur = ga.A1;
    int nW = ga.nW1;
    int wbase = 0;

    for (int sec = 0; sec < 2; sec++) {
        if (nW == 0) break;
        __syncthreads();
        conv_tile(Acur, m0, M, sm + SA, tid);

        for (int wi = 0; wi < nW; wi++) {
            const int w = wbase + wi;
            __syncthreads();
            copy_w(sm, ga.wh[w], tid);
            if (tid < 128) ((float*)(sm + S_BIAS))[tid] = ga.b[w] ? __ldg(ga.b[w] + tid) : 0.f;
            __syncthreads();

            float acc[2][4][4];
            gemm_core(smb, acc, arow0, akb, brow0, bkb);

            const int g = lane >> 2;
            const int tg = lane & 3;
            __half* __restrict__ C = ga.C[w];
            const float* sb = (const float*)(sm + S_BIAS);
#pragma unroll
            for (int ti = 0; ti < 2; ti++)
#pragma unroll
                for (int tj = 0; tj < 4; tj++) {
                    int row = m0 + wm * 32 + ti * 16 + g;
                    int col = wn * 32 + tj * 8 + tg * 2;
                    float2 bv = *(const float2*)(sb + col);
                    if (row < M)
                        *(__half2*)(C + (size_t)row * Hd + col) =
                            __floats2half2_rn(acc[ti][tj][0] + bv.x, acc[ti][tj][1] + bv.y);
                    if (row + 8 < M)
                        *(__half2*)(C + (size_t)(row + 8) * Hd + col) =
                            __floats2half2_rn(acc[ti][tj][2] + bv.x, acc[ti][tj][3] + bv.y);
                }
        }
        wbase += nW;
        Acur = ga.A2;
        nW = ga.nW2;
    }
}

// ---------------- pair pass 1: e = tanh(Ah[chi]+Bx[ci]) . v ; segmax ----------------
__global__ void pair_e_kernel(const int* __restrict__ ci, const int* __restrict__ chi,
                              const float* __restrict__ v, int L) {
    __shared__ float vs[Hd];
    if (threadIdx.x < Hd) vs[threadIdx.x] = v[threadIdx.x];
    __syncthreads();

    int w = blockIdx.x * (blockDim.x >> 5) + (threadIdx.x >> 5);
    int lane = threadIdx.x & 31;
    if (w >= L) return;

    int c  = __ldg(ci + w);
    int ch = __ldg(chi + w);
    float4 a  = ld_half4(g_Ahh + (size_t)ch * Hd + lane * 4);
    float4 b  = ld_half4(g_Bxh + (size_t)c * Hd + lane * 4);
    float4 vv = *(const float4*)(vs + lane * 4);

    float s = tanh_f(a.x + b.x) * vv.x + tanh_f(a.y + b.y) * vv.y +
              tanh_f(a.z + b.z) * vv.z + tanh_f(a.w + b.w) * vv.w;
#pragma unroll
    for (int o = 16; o; o >>= 1) s += __shfl_xor_sync(0xFFFFFFFFu, s, o);

    if (lane == 0) {
        g_e[w] = s;
        atomicMax(g_segmax + c, encf(s));
    }
}

// ---------------- pair pass 2: xexp = exp(e - segmax[ci]); segsum ----------------
__global__ void pair_exp_kernel(const int* __restrict__ ci, int L) {
    int l = blockIdx.x * blockDim.x + threadIdx.x;
    if (l >= L) return;
    int c = ci[l];
    float mx = decf(g_segmax[c]);
    float xe = __expf(g_e[l] - mx);
    g_e[l] = xe;
    atomicAdd(g_segsum + c, xe);
}

// ---------------- pair pass 3: h_hat and sum_f_c accumulation ----------------
__global__ void pair_acc_kernel(const int* __restrict__ ci, const int* __restrict__ chi,
                                int L) {
    int w = blockIdx.x * (blockDim.x >> 5) + (threadIdx.x >> 5);
    int lane = threadIdx.x & 31;
    if (w >= L) return;

    int c  = __ldg(ci + w);
    int ch = __ldg(chi + w);
    float attn = __ldg(g_e + w) / (__ldg(g_segsum + c) + SEPS);

    size_t co  = (size_t)c * Hd + lane * 4;
    size_t cho = (size_t)ch * Hd + lane * 4;

    float4 hv = ld_half4(g_chh + cho);
    red4(g_hhat + co, attn * hv.x, attn * hv.y, attn * hv.z, attn * hv.w);

    float4 wf = ld_half4(g_Wfxh + co);
    float4 uf = ld_half4(g_Ufhh + cho);
    float4 cv = ld_half4(g_cch + cho);
    float fx = sigm_f(wf.x + uf.x) * cv.x;
    float fy = sigm_f(wf.y + uf.y) * cv.y;
    float fz = sigm_f(wf.z + uf.z) * cv.z;
    float fw = sigm_f(wf.w + uf.w) * cv.w;
    red4(g_sumfc + co, fx, fy, fz, fw);
}

// ---------------- epilogue: gates -> h, c ----------------
__global__ void epilogue_kernel(float* __restrict__ outh, float* __restrict__ outc, int n4) {
    int stride = gridDim.x * blockDim.x;
    for (int i = blockIdx.x * blockDim.x + threadIdx.x; i < n4; i += stride) {
        size_t e = (size_t)i * 4;
        float4 wix = ld_half4(g_Wixh + e);
        float4 uih = ld_half4(g_Uihh + e);
        float4 wcx = ld_half4(g_Wcxh + e);
        float4 uch = ld_half4(g_Uchh + e);
        float4 wox = ld_half4(g_Woxh + e);
        float4 uoh = ld_half4(g_Uohh + e);
        float4 sf  = ((const float4*)g_sumfc)[i];

        float4 hc, cc;
        {
            float ig = sigm_f(wix.x + uih.x);
            float ct = tanh_f(wcx.x + uch.x);
            float cval = fmaf(ig, ct, sf.x);
            float og = sigm_f(wox.x + uoh.x);
            cc.x = cval; hc.x = og * tanh_f(cval);
        }
        {
            float ig = sigm_f(wix.y + uih.y);
            float ct = tanh_f(wcx.y + uch.y);
            float cval = fmaf(ig, ct, sf.y);
            float og = sigm_f(wox.y + uoh.y);
            cc.y = cval; hc.y = og * tanh_f(cval);
        }
        {
            float ig = sigm_f(wix.z + uih.z);
            float ct = tanh_f(wcx.z + uch.z);
            float cval = fmaf(ig, ct, sf.z);
            float og = sigm_f(wox.z + uoh.z);
            cc.z = cval; hc.z = og * tanh_f(cval);
        }
        {
            float ig = sigm_f(wix.w + uih.w);
            float ct = tanh_f(wcx.w + uch.w);
            float cval = fmaf(ig, ct, sf.w);
            float og = sigm_f(wox.w + uoh.w);
            cc.w = cval; hc.w = og * tanh_f(cval);
        }
        ((float4*)outh)[i] = hc;
        ((float4*)outc)[i] = cc;
    }
}

// ---------------- launch ----------------
extern "C" void kernel_launch(void* const* d_in, const int* in_sizes, int n_in,
                              void* d_out, int out_size) {
    const float* x_emb   = (const float*)d_in[0];
    const float* child_h = (const float*)d_in[1];
    const float* child_c = (const float*)d_in[2];
    const int*   ci      = (const int*)d_in[3];
    const int*   chi     = (const int*)d_in[4];
    const float* Wi_w = (const float*)d_in[5];
    const float* Ui_w = (const float*)d_in[6];
    const float* Wf_w = (const float*)d_in[7];
    const float* Uf_w = (const float*)d_in[8];
    const float* Wo_w = (const float*)d_in[9];
    const float* Uo_w = (const float*)d_in[10];
    const float* Wc_w = (const float*)d_in[11];
    const float* Uc_w = (const float*)d_in[12];
    const float* Wa_w = (const float*)d_in[13];
    const float* Ua_w = (const float*)d_in[14];
    const float* Wi_b = (const float*)d_in[15];
    const float* Wf_b = (const float*)d_in[16];
    const float* Wo_b = (const float*)d_in[17];
    const float* Wc_b = (const float*)d_in[18];
    const float* Wa_b = (const float*)d_in[19];
    const float* v_w  = (const float*)d_in[20];

    const int M = in_sizes[0] / Hd;
    const int L = in_sizes[3];

    float *p_hhat;
    cudaGetSymbolAddress((void**)&p_hhat, g_hhat);
    __half *p_Ahh, *p_Bxh, *p_Wfxh, *p_Ufhh, *p_Wixh, *p_Woxh, *p_Wcxh, *p_Uihh, *p_Uchh, *p_Uohh;
    cudaGetSymbolAddress((void**)&p_Ahh,  g_Ahh);
    cudaGetSymbolAddress((void**)&p_Bxh,  g_Bxh);
    cudaGetSymbolAddress((void**)&p_Wfxh, g_Wfxh);
    cudaGetSymbolAddress((void**)&p_Ufhh, g_Ufhh);
    cudaGetSymbolAddress((void**)&p_Wixh, g_Wixh);
    cudaGetSymbolAddress((void**)&p_Woxh, g_Woxh);
    cudaGetSymbolAddress((void**)&p_Wcxh, g_Wcxh);
    cudaGetSymbolAddress((void**)&p_Uihh, g_Uihh);
    cudaGetSymbolAddress((void**)&p_Uchh, g_Uchh);
    cudaGetSymbolAddress((void**)&p_Uohh, g_Uohh);
    char *p_wh;
    cudaGetSymbolAddress((void**)&p_wh, g_Wbh);

    float* outh = (float*)d_out;
    float* outc = outh + (size_t)M * Hd;

    const int mtiles = (M + 127) / 128;

    cudaFuncSetAttribute(gemm_mma, cudaFuncAttributeMaxDynamicSharedMemorySize, S_TOT1);

    // weight order in g_Wbh: 0:Ua 1:Wi 2:Wf 3:Wo 4:Wc 5:Wa 6:Uf 7:Ui 8:Uc 9:Uo
    {
        PrepArgs pa;
        pa.W[0] = Ua_w; pa.W[1] = Wi_w; pa.W[2] = Wf_w; pa.W[3] = Wo_w; pa.W[4] = Wc_w;
        pa.W[5] = Wa_w; pa.W[6] = Uf_w; pa.W[7] = Ui_w; pa.W[8] = Uc_w; pa.W[9] = Uo_w;
        pa.child_h = child_h;
        pa.child_c = child_c;
        prep_kernel<<<296, 256>>>(pa, M);
    }

    // phase 1: x-side (Bx, Wix, Wfx, Wox, Wcx) + child_h-side (Ah, Ufh), all fp16 out
    {
        TcArgs ga;
        ga.A1 = x_emb; ga.A2 = child_h; ga.nW1 = 5; ga.nW2 = 2; ga.M = M;
        int slot[7] = {0, 1, 2, 3, 4, 5, 6};
        const float* bs[7] = {nullptr, Wi_b, Wf_b, Wo_b, Wc_b, Wa_b, nullptr};
        __half* cs[7] = {p_Bxh, p_Wixh, p_Wfxh, p_Woxh, p_Wcxh, p_Ahh, p_Ufhh};
        for (int i = 0; i < 7; i++) {
            ga.wh[i] = p_wh + slot[i] * 32768;
            ga.b[i] = bs[i];
            ga.C[i] = cs[i];
        }
        gemm_mma<<<mtiles, NT, S_TOT1>>>(ga);
    }

    // attention + forget-gate pair passes
    pair_e_kernel<<<(L + 7) / 8, 256>>>(ci, chi, v_w, L);
    pair_exp_kernel<<<(L + 255) / 256, 256>>>(ci, L);
    pair_acc_kernel<<<(L + 7) / 8, 256>>>(ci, chi, L);

    // phase 3: h_hat-side (Uih, Uch, Uoh), fp16 out
    {
        TcArgs ga;
        ga.A1 = p_hhat; ga.A2 = nullptr; ga.nW1 = 3; ga.nW2 = 0; ga.M = M;
        int slot[7] = {7, 8, 9, 7, 7, 7, 7};
        __half* cs[7] = {p_Uihh, p_Uchh, p_Uohh, p_Uihh, p_Uihh, p_Uihh, p_Uihh};
        for (int i = 0; i < 7; i++) {
            ga.wh[i] = p_wh + slot[i] * 32768;
            ga.b[i] = nullptr;
            ga.C[i] = cs[i];
        }
        gemm_mma<<<mtiles, NT, S_TOT1>>>(ga);
    }

    const int n4 = M * Hd / 4;
    epilogue_kernel<<<(n4 + 255) / 256, 256>>>(outh, outc, n4);
}

// round 13
// speedup vs baseline: 1.3723x; 1.0333x over previous
#include <cuda_runtime.h>
#include <cuda_fp16.h>
#include <cstdint>

#define Hd 128
#define MAXM 50048
#define MAXL 400128
#define SEPS 1e-9f
#define NT 512

// ---------------- scratch (device globals; no allocations) ----------------
__device__ float g_hhat[MAXM*Hd];
__device__ float g_sumfc[MAXM*Hd];
// fp16 GEMM outputs / pair operands
__device__ __half g_Ahh [MAXM*Hd];
__device__ __half g_Bxh [MAXM*Hd];
__device__ __half g_Wfxh[MAXM*Hd];
__device__ __half g_Ufhh[MAXM*Hd];
__device__ __half g_Wixh[MAXM*Hd];
__device__ __half g_Woxh[MAXM*Hd];
__device__ __half g_Wcxh[MAXM*Hd];
__device__ __half g_Uihh[MAXM*Hd];
__device__ __half g_Uchh[MAXM*Hd];
__device__ __half g_Uohh[MAXM*Hd];
__device__ __half g_chh [MAXM*Hd];   // fp16 shadow of child_h
__device__ __half g_cch [MAXM*Hd];   // fp16 shadow of child_c
__device__ float g_e[MAXL];
__device__ float g_segsum[MAXM];
__device__ unsigned g_segmax[MAXM];
// pre-swizzled single-fp16 weights: 10 x 128x128, 32KB each
__device__ __align__(16) char g_Wbh[10 * 32768];

// ---------------- scalar helpers ----------------
__device__ __forceinline__ float sigm_f(float x) {
    return __fdividef(1.0f, 1.0f + __expf(-x));
}
__device__ __forceinline__ float tanh_f(float x) {
    float e2 = __expf(2.0f * x);
    return 1.0f - __fdividef(2.0f, e2 + 1.0f);
}
__device__ __forceinline__ unsigned encf(float f) {
    unsigned b = __float_as_uint(f);
    return (b & 0x80000000u) ? ~b : (b | 0x80000000u);
}
__device__ __forceinline__ float decf(unsigned u) {
    return (u & 0x80000000u) ? __uint_as_float(u ^ 0x80000000u) : __uint_as_float(~u);
}
__device__ __forceinline__ void red4(float* p, float x, float y, float z, float w) {
    asm volatile("red.global.add.v4.f32 [%0], {%1, %2, %3, %4};"
                 :: "l"(p), "f"(x), "f"(y), "f"(z), "f"(w) : "memory");
}
__device__ __forceinline__ uint32_t smem_u32(const void* p) {
    uint32_t a;
    asm("{ .reg .u64 t; cvta.to.shared.u64 t, %1; cvt.u32.u64 %0, t; }" : "=r"(a) : "l"(p));
    return a;
}
__device__ __forceinline__ float4 ld_half4(const __half* p) {
    uint2 v = *(const uint2*)p;
    float2 lo = __half22float2(*(__half2*)&v.x);
    float2 hi = __half22float2(*(__half2*)&v.y);
    return make_float4(lo.x, lo.y, hi.x, hi.y);
}
__device__ __forceinline__ uint32_t packh2(float x, float y) {
    __half2 h = __floats2half2_rn(x, y);
    return *(uint32_t*)&h;
}

// ---------------- cp.async helpers ----------------
__device__ __forceinline__ void cpasync16(uint32_t saddr, const void* g) {
    asm volatile("cp.async.cg.shared.global [%0], [%1], 16;" :: "r"(saddr), "l"(g));
}
#define CP_COMMIT() asm volatile("cp.async.commit_group;" ::: "memory")
#define CP_WAIT0()  asm volatile("cp.async.wait_group 0;" ::: "memory")

// ---------------- mma / ldmatrix wrappers ----------------
__device__ __forceinline__ void ldm4(uint32_t* r, uint32_t addr) {
    asm volatile("ldmatrix.sync.aligned.m8n8.x4.shared.b16 {%0,%1,%2,%3}, [%4];"
                 : "=r"(r[0]), "=r"(r[1]), "=r"(r[2]), "=r"(r[3]) : "r"(addr));
}
__device__ __forceinline__ void mma16816h(float* d, const uint32_t* a, const uint32_t* b) {
    asm volatile("mma.sync.aligned.m16n8k16.row.col.f32.f16.f16.f32 "
                 "{%0,%1,%2,%3}, {%4,%5,%6,%7}, {%8,%9}, {%0,%1,%2,%3};"
                 : "+f"(d[0]), "+f"(d[1]), "+f"(d[2]), "+f"(d[3])
                 : "r"(a[0]), "r"(a[1]), "r"(a[2]), "r"(a[3]), "r"(b[0]), "r"(b[1]));
}

// swizzled byte offset of (row, colbyte) in a 128-row x 256B tile
__device__ __forceinline__ uint32_t swz(int row, int colbyte) {
    return (uint32_t)(row * 256 + (colbyte ^ ((row & 7) << 4)));
}

// ---------------- prep: zero accum + fp16 weights + fp16 shadows ----------------
struct PrepArgs { const float* W[10]; const float* child_h; const float* child_c; };

__global__ void prep_kernel(PrepArgs pa, int M) {
    int stride = gridDim.x * blockDim.x;
    int gt = blockIdx.x * blockDim.x + threadIdx.x;
    int n4 = M * Hd / 4;
    float4 z = make_float4(0.f, 0.f, 0.f, 0.f);
    for (int i = gt; i < n4; i += stride) {
        ((float4*)g_hhat)[i]  = z;
        ((float4*)g_sumfc)[i] = z;
    }
    for (int i = gt; i < M; i += stride) {
        g_segsum[i] = 0.f;
        g_segmax[i] = 0u;
    }
    // weights -> single fp16, pre-swizzled
    for (int idx = gt; idx < 10 * 8192; idx += stride) {
        int w = idx >> 13;
        int i = idx & 8191;
        int row = i >> 6;
        int c2 = i & 63;
        float2 v = *(const float2*)(pa.W[w] + (size_t)row * Hd + c2 * 2);
        *(uint32_t*)(g_Wbh + w * 32768 + swz(row, c2 * 4)) = packh2(v.x, v.y);
    }
    // fp16 shadows of child_h, child_c
    int n2 = M * Hd / 2;
    for (int i = gt; i < n2; i += stride) {
        float2 vh = ((const float2*)pa.child_h)[i];
        float2 vc = ((const float2*)pa.child_c)[i];
        ((__half2*)g_chh)[i] = __floats2half2_rn(vh.x, vh.y);
        ((__half2*)g_cch)[i] = __floats2half2_rn(vc.x, vc.y);
    }
}

// ---------------- shared GEMM building blocks ----------------
#define SA    0
#define SW0   32768
#define S_TOT1 (32768 * 3)

__device__ __forceinline__ void conv_tile(const float* __restrict__ A, int m0, int M,
                                          char* dst, int tid) {
#pragma unroll
    for (int it = 0; it < 8192 / NT; it++) {
        int i = tid + it * NT;
        int row = i >> 6;
        int c2 = i & 63;
        float2 v = make_float2(0.f, 0.f);
        if (m0 + row < M) v = *(const float2*)(A + (size_t)(m0 + row) * Hd + c2 * 2);
        *(uint32_t*)(dst + swz(row, c2 * 4)) = packh2(v.x, v.y);
    }
}

// async fetch of one 32KB weight tile into smem buffer
__device__ __forceinline__ void prefetch_w(uint32_t sbuf, const char* wh, int tid) {
#pragma unroll
    for (int it = 0; it < 2048 / NT; it++) {
        int i = tid + it * NT;
        cpasync16(sbuf + i * 16, wh + i * 16);
    }
    CP_COMMIT();
}

// compute 128x128 fp16 gemm tile into acc[2][4][4]
__device__ __forceinline__ void gemm_core(const uint32_t smb, uint32_t swoff,
                                          float acc[2][4][4],
                                          int arow0, int akb, int brow0, int bkb) {
#pragma unroll
    for (int ti = 0; ti < 2; ti++)
#pragma unroll
        for (int tj = 0; tj < 4; tj++)
#pragma unroll
            for (int k = 0; k < 4; k++) acc[ti][tj][k] = 0.f;

#pragma unroll
    for (int ks = 0; ks < 8; ks++) {
        const int kb0 = ks * 32;
        uint32_t ah[2][4], bh[2][4];
#pragma unroll
        for (int ti = 0; ti < 2; ti++) {
            int row = arow0 + ti * 16;
            ldm4(ah[ti], smb + SA + swz(row, kb0 + akb));
        }
#pragma unroll
        for (int tp = 0; tp < 2; tp++) {
            int row = brow0 + tp * 16;
            ldm4(bh[tp], smb + swoff + swz(row, kb0 + bkb));
        }
#pragma unroll
        for (int ti = 0; ti < 2; ti++)
#pragma unroll
            for (int tj = 0; tj < 4; tj++) {
                const uint32_t* bp = &bh[tj >> 1][(tj & 1) * 2];
                mma16816h(acc[ti][tj], ah[ti], bp);
            }
    }
}

// ---------------- batched GEMM: fp16 outputs, double-buffered weights ----------------
struct TcArgs {
    const float* A1;
    const float* A2;
    const char* wh[7];
    const float* b[7];
    __half* C[7];
    int nW1, nW2, M;
};

__global__ void __launch_bounds__(NT, 1) gemm_mma(TcArgs ga) {
    extern __shared__ char sm[];
    const uint32_t smb = smem_u32(sm);
    const int tid = threadIdx.x;
    const int wid = tid >> 5;
    const int lane = tid & 31;
    const int m0 = blockIdx.x * 128;
    const int M = ga.M;
    const int wm = wid >> 2;
    const int wn = wid & 3;
    const int sub = lane & 7;
    const int quad = lane >> 3;
    const int arow0 = wm * 32 + sub + (quad & 1) * 8;
    const int akb   = (quad >> 1) * 16;
    const int brow0 = wn * 32 + sub + (quad >> 1) * 8;
    const int bkb   = (quad & 1) * 16;
    const int g = lane >> 2;
    const int tg = lane & 3;

    const int nWtot = ga.nW1 + ga.nW2;

    // prologue: async-fetch weight 0, convert first A tile
    prefetch_w(smb + SW0, ga.wh[0], tid);
    conv_tile(ga.A1, m0, M, sm + SA, tid);

    int cur = 0;
    for (int w = 0; w < nWtot; w++) {
        CP_WAIT0();
        __syncthreads();                  // weight buf(cur) + A tile visible

        if (w == ga.nW1) {
            // switch A operand to A2 (prior gemm readers of SA passed the sync)
            conv_tile(ga.A2, m0, M, sm + SA, tid);
        }
        if (w + 1 < nWtot)
            prefetch_w(smb + SW0 + (cur ^ 1) * 32768, ga.wh[w + 1], tid);
        if (w == ga.nW1)
            __syncthreads();              // new A tile visible

        float acc[2][4][4];
        gemm_core(smb, SW0 + cur * 32768, acc, arow0, akb, brow0, bkb);

        // store fp16 C tile (+bias via __ldg; bias is 512B, L2-broadcast)
        const float* bias = ga.b[w];
        __half* __restrict__ C = ga.C[w];
#pragma unroll
        for (int ti = 0; ti < 2; ti++)
#pragma unroll
            for (int tj = 0; tj < 4; tj++) {
                int row = m0 + wm * 32 + ti * 16 + g;
                int col = wn * 32 + tj * 8 + tg * 2;
                float2 bv = bias ? *(const float2*)(bias + col) : make_float2(0.f, 0.f);
                if (row < M)
                    *(__half2*)(C + (size_t)row * Hd + col) =
                        __floats2half2_rn(acc[ti][tj][0] + bv.x, acc[ti][tj][1] + bv.y);
                if (row + 8 < M)
                    *(__half2*)(C + (size_t)(row + 8) * Hd + col) =
                        __floats2half2_rn(acc[ti][tj][2] + bv.x, acc[ti][tj][3] + bv.y);
            }
        cur ^= 1;
        __syncthreads();                  // all reads of buf(cur^1) done before its refill next iter
    }
}

// ---------------- pair pass 1: e = tanh(Ah[chi]+Bx[ci]) . v ; segmax ----------------
__global__ void pair_e_kernel(const int* __restrict__ ci, const int* __restrict__ chi,
                              const float* __restrict__ v, int L) {
    __shared__ float vs[Hd];
    if (threadIdx.x < Hd) vs[threadIdx.x] = v[threadIdx.x];
    __syncthreads();

    int w = blockIdx.x * (blockDim.x >> 5) + (threadIdx.x >> 5);
    int lane = threadIdx.x & 31;
    if (w >= L) return;

    int c  = __ldg(ci + w);
    int ch = __ldg(chi + w);
    float4 a  = ld_half4(g_Ahh + (size_t)ch * Hd + lane * 4);
    float4 b  = ld_half4(g_Bxh + (size_t)c * Hd + lane * 4);
    float4 vv = *(const float4*)(vs + lane * 4);

    float s = tanh_f(a.x + b.x) * vv.x + tanh_f(a.y + b.y) * vv.y +
              tanh_f(a.z + b.z) * vv.z + tanh_f(a.w + b.w) * vv.w;
#pragma unroll
    for (int o = 16; o; o >>= 1) s += __shfl_xor_sync(0xFFFFFFFFu, s, o);

    if (lane == 0) {
        g_e[w] = s;
        atomicMax(g_segmax + c, encf(s));
    }
}

// ---------------- pair pass 2: xexp = exp(e - segmax[ci]); segsum ----------------
__global__ void pair_exp_kernel(const int* __restrict__ ci, int L) {
    int l = blockIdx.x * blockDim.x + threadIdx.x;
    if (l >= L) return;
    int c = ci[l];
    float mx = decf(g_segmax[c]);
    float xe = __expf(g_e[l] - mx);
    g_e[l] = xe;
    atomicAdd(g_segsum + c, xe);
}

// ---------------- pair pass 3: h_hat and sum_f_c accumulation ----------------
__global__ void pair_acc_kernel(const int* __restrict__ ci, const int* __restrict__ chi,
                                int L) {
    int w = blockIdx.x * (blockDim.x >> 5) + (threadIdx.x >> 5);
    int lane = threadIdx.x & 31;
    if (w >= L) return;

    int c  = __ldg(ci + w);
    int ch = __ldg(chi + w);
    float attn = __ldg(g_e + w) / (__ldg(g_segsum + c) + SEPS);

    size_t co  = (size_t)c * Hd + lane * 4;
    size_t cho = (size_t)ch * Hd + lane * 4;

    float4 hv = ld_half4(g_chh + cho);
    red4(g_hhat + co, attn * hv.x, attn * hv.y, attn * hv.z, attn * hv.w);

    float4 wf = ld_half4(g_Wfxh + co);
    float4 uf = ld_half4(g_Ufhh + cho);
    float4 cv = ld_half4(g_cch + cho);
    float fx = sigm_f(wf.x + uf.x) * cv.x;
    float fy = sigm_f(wf.y + uf.y) * cv.y;
    float fz = sigm_f(wf.z + uf.z) * cv.z;
    float fw = sigm_f(wf.w + uf.w) * cv.w;
    red4(g_sumfc + co, fx, fy, fz, fw);
}

// ---------------- epilogue: gates -> h, c ----------------
__global__ void epilogue_kernel(float* __restrict__ outh, float* __restrict__ outc, int n4) {
    int stride = gridDim.x * blockDim.x;
    for (int i = blockIdx.x * blockDim.x + threadIdx.x; i < n4; i += stride) {
        size_t e = (size_t)i * 4;
        float4 wix = ld_half4(g_Wixh + e);
        float4 uih = ld_half4(g_Uihh + e);
        float4 wcx = ld_half4(g_Wcxh + e);
        float4 uch = ld_half4(g_Uchh + e);
        float4 wox = ld_half4(g_Woxh + e);
        float4 uoh = ld_half4(g_Uohh + e);
        float4 sf  = ((const float4*)g_sumfc)[i];

        float4 hc, cc;
        {
            float ig = sigm_f(wix.x + uih.x);
            float ct = tanh_f(wcx.x + uch.x);
            float cval = fmaf(ig, ct, sf.x);
            float og = sigm_f(wox.x + uoh.x);
            cc.x = cval; hc.x = og * tanh_f(cval);
        }
        {
            float ig = sigm_f(wix.y + uih.y);
            float ct = tanh_f(wcx.y + uch.y);
            float cval = fmaf(ig, ct, sf.y);
            float og = sigm_f(wox.y + uoh.y);
            cc.y = cval; hc.y = og * tanh_f(cval);
        }
        {
            float ig = sigm_f(wix.z + uih.z);
            float ct = tanh_f(wcx.z + uch.z);
            float cval = fmaf(ig, ct, sf.z);
            float og = sigm_f(wox.z + uoh.z);
            cc.z = cval; hc.z = og * tanh_f(cval);
        }
        {
            float ig = sigm_f(wix.w + uih.w);
            float ct = tanh_f(wcx.w + uch.w);
            float cval = fmaf(ig, ct, sf.w);
            float og = sigm_f(wox.w + uoh.w);
            cc.w = cval; hc.w = og * tanh_f(cval);
        }
        ((float4*)outh)[i] = hc;
        ((float4*)outc)[i] = cc;
    }
}

// ---------------- launch ----------------
extern "C" void kernel_launch(void* const* d_in, const int* in_sizes, int n_in,
                              void* d_out, int out_size) {
    const float* x_emb   = (const float*)d_in[0];
    const float* child_h = (const float*)d_in[1];
    const float* child_c = (const float*)d_in[2];
    const int*   ci      = (const int*)d_in[3];
    const int*   chi     = (const int*)d_in[4];
    const float* Wi_w = (const float*)d_in[5];
    const float* Ui_w = (const float*)d_in[6];
    const float* Wf_w = (const float*)d_in[7];
    const float* Uf_w = (const float*)d_in[8];
    const float* Wo_w = (const float*)d_in[9];
    const float* Uo_w = (const float*)d_in[10];
    const float* Wc_w = (const float*)d_in[11];
    const float* Uc_w = (const float*)d_in[12];
    const float* Wa_w = (const float*)d_in[13];
    const float* Ua_w = (const float*)d_in[14];
    const float* Wi_b = (const float*)d_in[15];
    const float* Wf_b = (const float*)d_in[16];
    const float* Wo_b = (const float*)d_in[17];
    const float* Wc_b = (const float*)d_in[18];
    const float* Wa_b = (const float*)d_in[19];
    const float* v_w  = (const float*)d_in[20];

    const int M = in_sizes[0] / Hd;
    const int L = in_sizes[3];

    float *p_hhat;
    cudaGetSymbolAddress((void**)&p_hhat, g_hhat);
    __half *p_Ahh, *p_Bxh, *p_Wfxh, *p_Ufhh, *p_Wixh, *p_Woxh, *p_Wcxh, *p_Uihh, *p_Uchh, *p_Uohh;
    cudaGetSymbolAddress((void**)&p_Ahh,  g_Ahh);
    cudaGetSymbolAddress((void**)&p_Bxh,  g_Bxh);
    cudaGetSymbolAddress((void**)&p_Wfxh, g_Wfxh);
    cudaGetSymbolAddress((void**)&p_Ufhh, g_Ufhh);
    cudaGetSymbolAddress((void**)&p_Wixh, g_Wixh);
    cudaGetSymbolAddress((void**)&p_Woxh, g_Woxh);
    cudaGetSymbolAddress((void**)&p_Wcxh, g_Wcxh);
    cudaGetSymbolAddress((void**)&p_Uihh, g_Uihh);
    cudaGetSymbolAddress((void**)&p_Uchh, g_Uchh);
    cudaGetSymbolAddress((void**)&p_Uohh, g_Uohh);
    char *p_wh;
    cudaGetSymbolAddress((void**)&p_wh, g_Wbh);

    float* outh = (float*)d_out;
    float* outc = outh + (size_t)M * Hd;

    const int mtiles = (M + 127) / 128;

    cudaFuncSetAttribute(gemm_mma, cudaFuncAttributeMaxDynamicSharedMemorySize, S_TOT1);

    // weight order in g_Wbh: 0:Ua 1:Wi 2:Wf 3:Wo 4:Wc 5:Wa 6:Uf 7:Ui 8:Uc 9:Uo
    {
        PrepArgs pa;
        pa.W[0] = Ua_w; pa.W[1] = Wi_w; pa.W[2] = Wf_w; pa.W[3] = Wo_w; pa.W[4] = Wc_w;
        pa.W[5] = Wa_w; pa.W[6] = Uf_w; pa.W[7] = Ui_w; pa.W[8] = Uc_w; pa.W[9] = Uo_w;
        pa.child_h = child_h;
        pa.child_c = child_c;
        prep_kernel<<<296, 256>>>(pa, M);
    }

    // phase 1: x-side (Bx, Wix, Wfx, Wox, Wcx) + child_h-side (Ah, Ufh), all fp16 out
    {
        TcArgs ga;
        ga.A1 = x_emb; ga.A2 = child_h; ga.nW1 = 5; ga.nW2 = 2; ga.M = M;
        int slot[7] = {0, 1, 2, 3, 4, 5, 6};
        const float* bs[7] = {nullptr, Wi_b, Wf_b, Wo_b, Wc_b, Wa_b, nullptr};
        __half* cs[7] = {p_Bxh, p_Wixh, p_Wfxh, p_Woxh, p_Wcxh, p_Ahh, p_Ufhh};
        for (int i = 0; i < 7; i++) {
            ga.wh[i] = p_wh + slot[i] * 32768;
            ga.b[i] = bs[i];
            ga.C[i] = cs[i];
        }
        gemm_mma<<<mtiles, NT, S_TOT1>>>(ga);
    }

    // attention + forget-gate pair passes
    pair_e_kernel<<<(L + 7) / 8, 256>>>(ci, chi, v_w, L);
    pair_exp_kernel<<<(L + 255) / 256, 256>>>(ci, L);
    pair_acc_kernel<<<(L + 7) / 8, 256>>>(ci, chi, L);

    // phase 3: h_hat-side (Uih, Uch, Uoh), fp16 out
    {
        TcArgs ga;
        ga.A1 = p_hhat; ga.A2 = nullptr; ga.nW1 = 3; ga.nW2 = 0; ga.M = M;
        int slot[7] = {7, 8, 9, 7, 7, 7, 7};
        __half* cs[7] = {p_Uihh, p_Uchh, p_Uohh, p_Uihh, p_Uihh, p_Uihh, p_Uihh};
        for (int i = 0; i < 7; i++) {
            ga.wh[i] = p_wh + slot[i] * 32768;
            ga.b[i] = nullptr;
            ga.C[i] = cs[i];
        }
        gemm_mma<<<mtiles, NT, S_TOT1>>>(ga);
    }

    const int n4 = M * Hd / 4;
    epilogue_kernel<<<(n4 + 255) / 256, 256>>>(outh, outc, n4);
}

// round 14
// speedup vs baseline: 1.5298x; 1.1148x over previous
#include <cuda_runtime.h>
#include <cuda_fp16.h>
#include <cstdint>

#define Hd 128
#define MAXM 50048
#define MAXL 400128
#define SEPS 1e-9f
#define NT 512

// ---------------- scratch (device globals; no allocations) ----------------
__device__ float g_hhat[MAXM*Hd];
__device__ float g_sumfc[MAXM*Hd];
// fp16 GEMM outputs / pair operands
__device__ __half g_Ahh [MAXM*Hd];
__device__ __half g_Bxh [MAXM*Hd];
__device__ __half g_Wfxh[MAXM*Hd];
__device__ __half g_Ufhh[MAXM*Hd];
__device__ __half g_Wixh[MAXM*Hd];
__device__ __half g_Woxh[MAXM*Hd];
__device__ __half g_Wcxh[MAXM*Hd];
__device__ __half g_Uihh[MAXM*Hd];
__device__ __half g_Uchh[MAXM*Hd];
__device__ __half g_Uohh[MAXM*Hd];
__device__ __half g_chh [MAXM*Hd];   // fp16 shadow of child_h
__device__ __half g_cch [MAXM*Hd];   // fp16 shadow of child_c
// counting sort of pairs by ci
__device__ int g_cnt[MAXM];
__device__ int g_off[MAXM];
__device__ int g_cursor[MAXM];
__device__ int g_blk[64];
__device__ int g_sorted[MAXL];
// pre-swizzled single-fp16 weights: 10 x 128x128, 32KB each
__device__ __align__(16) char g_Wbh[10 * 32768];

// ---------------- scalar helpers ----------------
__device__ __forceinline__ float sigm_f(float x) {
    return __fdividef(1.0f, 1.0f + __expf(-x));
}
__device__ __forceinline__ float tanh_f(float x) {
    float e2 = __expf(2.0f * x);
    return 1.0f - __fdividef(2.0f, e2 + 1.0f);
}
__device__ __forceinline__ uint32_t smem_u32(const void* p) {
    uint32_t a;
    asm("{ .reg .u64 t; cvta.to.shared.u64 t, %1; cvt.u32.u64 %0, t; }" : "=r"(a) : "l"(p));
    return a;
}
__device__ __forceinline__ float4 ld_half4(const __half* p) {
    uint2 v = *(const uint2*)p;
    float2 lo = __half22float2(*(__half2*)&v.x);
    float2 hi = __half22float2(*(__half2*)&v.y);
    return make_float4(lo.x, lo.y, hi.x, hi.y);
}
__device__ __forceinline__ uint32_t packh2(float x, float y) {
    __half2 h = __floats2half2_rn(x, y);
    return *(uint32_t*)&h;
}

// ---------------- cp.async helpers ----------------
__device__ __forceinline__ void cpasync16(uint32_t saddr, const void* g) {
    asm volatile("cp.async.cg.shared.global [%0], [%1], 16;" :: "r"(saddr), "l"(g));
}
#define CP_COMMIT() asm volatile("cp.async.commit_group;" ::: "memory")
#define CP_WAIT0()  asm volatile("cp.async.wait_group 0;" ::: "memory")

// ---------------- mma / ldmatrix wrappers ----------------
__device__ __forceinline__ void ldm4(uint32_t* r, uint32_t addr) {
    asm volatile("ldmatrix.sync.aligned.m8n8.x4.shared.b16 {%0,%1,%2,%3}, [%4];"
                 : "=r"(r[0]), "=r"(r[1]), "=r"(r[2]), "=r"(r[3]) : "r"(addr));
}
__device__ __forceinline__ void mma16816h(float* d, const uint32_t* a, const uint32_t* b) {
    asm volatile("mma.sync.aligned.m16n8k16.row.col.f32.f16.f16.f32 "
                 "{%0,%1,%2,%3}, {%4,%5,%6,%7}, {%8,%9}, {%0,%1,%2,%3};"
                 : "+f"(d[0]), "+f"(d[1]), "+f"(d[2]), "+f"(d[3])
                 : "r"(a[0]), "r"(a[1]), "r"(a[2]), "r"(a[3]), "r"(b[0]), "r"(b[1]));
}

// swizzled byte offset of (row, colbyte) in a 128-row x 256B tile
__device__ __forceinline__ uint32_t swz(int row, int colbyte) {
    return (uint32_t)(row * 256 + (colbyte ^ ((row & 7) << 4)));
}

// ---------------- prep: zero counters + fp16 weights + fp16 shadows ----------------
struct PrepArgs { const float* W[10]; const float* child_h; const float* child_c; };

__global__ void prep_kernel(PrepArgs pa, int M) {
    int stride = gridDim.x * blockDim.x;
    int gt = blockIdx.x * blockDim.x + threadIdx.x;
    for (int i = gt; i < MAXM; i += stride) g_cnt[i] = 0;
    // weights -> single fp16, pre-swizzled
    for (int idx = gt; idx < 10 * 8192; idx += stride) {
        int w = idx >> 13;
        int i = idx & 8191;
        int row = i >> 6;
        int c2 = i & 63;
        float2 v = *(const float2*)(pa.W[w] + (size_t)row * Hd + c2 * 2);
        *(uint32_t*)(g_Wbh + w * 32768 + swz(row, c2 * 4)) = packh2(v.x, v.y);
    }
    // fp16 shadows of child_h, child_c
    int n2 = M * Hd / 2;
    for (int i = gt; i < n2; i += stride) {
        float2 vh = ((const float2*)pa.child_h)[i];
        float2 vc = ((const float2*)pa.child_c)[i];
        ((__half2*)g_chh)[i] = __floats2half2_rn(vh.x, vh.y);
        ((__half2*)g_cch)[i] = __floats2half2_rn(vc.x, vc.y);
    }
}

// ---------------- counting sort of pairs by ci ----------------
__global__ void hist_kernel(const int* __restrict__ ci, int L) {
    int stride = gridDim.x * blockDim.x;
    for (int l = blockIdx.x * blockDim.x + threadIdx.x; l < L; l += stride)
        atomicAdd(&g_cnt[ci[l]], 1);
}

// per-1024-block exclusive scan; 256 threads, 4 elems/thread
__global__ void scan1_kernel() {
    __shared__ int warp_tot[8];
    __shared__ int warp_off[8];
    int t = threadIdx.x;
    int lane = t & 31;
    int wid = t >> 5;
    int base = blockIdx.x * 1024 + t * 4;
    int v0 = base + 0 < MAXM ? g_cnt[base + 0] : 0;
    int v1 = base + 1 < MAXM ? g_cnt[base + 1] : 0;
    int v2 = base + 2 < MAXM ? g_cnt[base + 2] : 0;
    int v3 = base + 3 < MAXM ? g_cnt[base + 3] : 0;
    int p1 = v0, p2 = v0 + v1, p3 = v0 + v1 + v2;
    int tsum = p3 + v3;
    int x = tsum;
#pragma unroll
    for (int o = 1; o < 32; o <<= 1) {
        int y = __shfl_up_sync(0xFFFFFFFFu, x, o);
        if (lane >= o) x += y;
    }
    if (lane == 31) warp_tot[wid] = x;
    __syncthreads();
    if (t == 0) {
        int r = 0;
#pragma unroll
        for (int i = 0; i < 8; i++) { warp_off[i] = r; r += warp_tot[i]; }
        g_blk[blockIdx.x] = r;
    }
    __syncthreads();
    int excl = x - tsum + warp_off[wid];
    if (base + 0 < MAXM) g_off[base + 0] = excl;
    if (base + 1 < MAXM) g_off[base + 1] = excl + p1;
    if (base + 2 < MAXM) g_off[base + 2] = excl + p2;
    if (base + 3 < MAXM) g_off[base + 3] = excl + p3;
}

__global__ void scan2_kernel(int nblk) {
    if (threadIdx.x == 0 && blockIdx.x == 0) {
        int r = 0;
        for (int i = 0; i < nblk; i++) { int t = g_blk[i]; g_blk[i] = r; r += t; }
    }
}

__global__ void fixup_kernel() {
    int stride = gridDim.x * blockDim.x;
    for (int i = blockIdx.x * blockDim.x + threadIdx.x; i < MAXM; i += stride) {
        int o = g_off[i] + g_blk[i >> 10];
        g_off[i] = o;
        g_cursor[i] = o;
    }
}

__global__ void scatter_kernel(const int* __restrict__ ci, int L) {
    int stride = gridDim.x * blockDim.x;
    for (int l = blockIdx.x * blockDim.x + threadIdx.x; l < L; l += stride) {
        int pos = atomicAdd(&g_cursor[ci[l]], 1);
        g_sorted[pos] = l;
    }
}

// ---------------- fused segment kernel: softmax attention + forget gate ----------------
// one warp per segment m; online softmax; plain stores (warp owns row m exclusively)
__global__ void seg_kernel(const int* __restrict__ chi, const float* __restrict__ v,
                           int M) {
    __shared__ float vs[Hd];
    if (threadIdx.x < Hd) vs[threadIdx.x] = v[threadIdx.x];
    __syncthreads();

    int m = blockIdx.x * (blockDim.x >> 5) + (threadIdx.x >> 5);
    int lane = threadIdx.x & 31;
    if (m >= M) return;

    int start = __ldg(g_off + m);
    int end   = __ldg(g_cursor + m);   // after scatter, cursor == segment end

    size_t mo = (size_t)m * Hd + lane * 4;
    float4 vv = *(const float4*)(vs + lane * 4);
    float4 bx = ld_half4(g_Bxh + mo);
    float4 wf = ld_half4(g_Wfxh + mo);

    float runm = -3.4e38f, s = 0.f;
    float4 acch = make_float4(0.f, 0.f, 0.f, 0.f);
    float4 accf = make_float4(0.f, 0.f, 0.f, 0.f);

    for (int p = start; p < end; p++) {
        int l = __ldg(g_sorted + p);
        int ch = __ldg(chi + l);
        size_t cho = (size_t)ch * Hd + lane * 4;

        float4 a = ld_half4(g_Ahh + cho);
        float e = tanh_f(a.x + bx.x) * vv.x + tanh_f(a.y + bx.y) * vv.y +
                  tanh_f(a.z + bx.z) * vv.z + tanh_f(a.w + bx.w) * vv.w;
#pragma unroll
        for (int o = 16; o; o >>= 1) e += __shfl_xor_sync(0xFFFFFFFFu, e, o);

        float mnew = fmaxf(runm, e);
        float scale = __expf(runm - mnew);   // 0 on first pair (runm = -big)
        float xe = __expf(e - mnew);
        s = s * scale + xe;

        float4 hv = ld_half4(g_chh + cho);
        acch.x = acch.x * scale + xe * hv.x;
        acch.y = acch.y * scale + xe * hv.y;
        acch.z = acch.z * scale + xe * hv.z;
        acch.w = acch.w * scale + xe * hv.w;

        float4 uf = ld_half4(g_Ufhh + cho);
        float4 cv = ld_half4(g_cch + cho);
        accf.x += sigm_f(wf.x + uf.x) * cv.x;
        accf.y += sigm_f(wf.y + uf.y) * cv.y;
        accf.z += sigm_f(wf.z + uf.z) * cv.z;
        accf.w += sigm_f(wf.w + uf.w) * cv.w;

        runm = mnew;
    }

    float inv = __fdividef(1.0f, s + SEPS);
    float4 hh = make_float4(acch.x * inv, acch.y * inv, acch.z * inv, acch.w * inv);
    *(float4*)(g_hhat + mo)  = hh;
    *(float4*)(g_sumfc + mo) = accf;
}

// ---------------- shared GEMM building blocks ----------------
#define SA    0
#define SW0   32768
#define S_TOT1 (32768 * 3)

__device__ __forceinline__ void conv_tile(const float* __restrict__ A, int m0, int M,
                                          char* dst, int tid) {
#pragma unroll
    for (int it = 0; it < 8192 / NT; it++) {
        int i = tid + it * NT;
        int row = i >> 6;
        int c2 = i & 63;
        float2 v = make_float2(0.f, 0.f);
        if (m0 + row < M) v = *(const float2*)(A + (size_t)(m0 + row) * Hd + c2 * 2);
        *(uint32_t*)(dst + swz(row, c2 * 4)) = packh2(v.x, v.y);
    }
}

// async fetch of one 32KB weight tile into smem buffer
__device__ __forceinline__ void prefetch_w(uint32_t sbuf, const char* wh, int tid) {
#pragma unroll
    for (int it = 0; it < 2048 / NT; it++) {
        int i = tid + it * NT;
        cpasync16(sbuf + i * 16, wh + i * 16);
    }
    CP_COMMIT();
}

// compute 128x128 fp16 gemm tile into acc[2][4][4]
__device__ __forceinline__ void gemm_core(const uint32_t smb, uint32_t swoff,
                                          float acc[2][4][4],
                                          int arow0, int akb, int brow0, int bkb) {
#pragma unroll
    for (int ti = 0; ti < 2; ti++)
#pragma unroll
        for (int tj = 0; tj < 4; tj++)
#pragma unroll
            for (int k = 0; k < 4; k++) acc[ti][tj][k] = 0.f;

#pragma unroll
    for (int ks = 0; ks < 8; ks++) {
        const int kb0 = ks * 32;
        uint32_t ah[2][4], bh[2][4];
#pragma unroll
        for (int ti = 0; ti < 2; ti++) {
            int row = arow0 + ti * 16;
            ldm4(ah[ti], smb + SA + swz(row, kb0 + akb));
        }
#pragma unroll
        for (int tp = 0; tp < 2; tp++) {
            int row = brow0 + tp * 16;
            ldm4(bh[tp], smb + swoff + swz(row, kb0 + bkb));
        }
#pragma unroll
        for (int ti = 0; ti < 2; ti++)
#pragma unroll
            for (int tj = 0; tj < 4; tj++) {
                const uint32_t* bp = &bh[tj >> 1][(tj & 1) * 2];
                mma16816h(acc[ti][tj], ah[ti], bp);
            }
    }
}

// ---------------- batched GEMM: fp16 outputs, double-buffered weights ----------------
struct TcArgs {
    const float* A1;
    const float* A2;
    const char* wh[7];
    const float* b[7];
    __half* C[7];
    int nW1, nW2, M;
};

__global__ void __launch_bounds__(NT, 1) gemm_mma(TcArgs ga) {
    extern __shared__ char sm[];
    const uint32_t smb = smem_u32(sm);
    const int tid = threadIdx.x;
    const int wid = tid >> 5;
    const int lane = tid & 31;
    const int m0 = blockIdx.x * 128;
    const int M = ga.M;
    const int wm = wid >> 2;
    const int wn = wid & 3;
    const int sub = lane & 7;
    const int quad = lane >> 3;
    const int arow0 = wm * 32 + sub + (quad & 1) * 8;
    const int akb   = (quad >> 1) * 16;
    const int brow0 = wn * 32 + sub + (quad >> 1) * 8;
    const int bkb   = (quad & 1) * 16;
    const int g = lane >> 2;
    const int tg = lane & 3;

    const int nWtot = ga.nW1 + ga.nW2;

    // prologue: async-fetch weight 0, convert first A tile
    prefetch_w(smb + SW0, ga.wh[0], tid);
    conv_tile(ga.A1, m0, M, sm + SA, tid);

    int cur = 0;
    for (int w = 0; w < nWtot; w++) {
        CP_WAIT0();
        __syncthreads();                  // weight buf(cur) + A tile visible

        if (w == ga.nW1) {
            // switch A operand to A2 (prior gemm readers of SA passed the sync)
            conv_tile(ga.A2, m0, M, sm + SA, tid);
        }
        if (w + 1 < nWtot)
            prefetch_w(smb + SW0 + (cur ^ 1) * 32768, ga.wh[w + 1], tid);
        if (w == ga.nW1)
            __syncthreads();              // new A tile visible

        float acc[2][4][4];
        gemm_core(smb, SW0 + cur * 32768, acc, arow0, akb, brow0, bkb);

        // store fp16 C tile (+bias via __ldg; bias is 512B, L2-broadcast)
        const float* bias = ga.b[w];
        __half* __restrict__ C = ga.C[w];
#pragma unroll
        for (int ti = 0; ti < 2; ti++)
#pragma unroll
            for (int tj = 0; tj < 4; tj++) {
                int row = m0 + wm * 32 + ti * 16 + g;
                int col = wn * 32 + tj * 8 + tg * 2;
                float2 bv = bias ? *(const float2*)(bias + col) : make_float2(0.f, 0.f);
                if (row < M)
                    *(__half2*)(C + (size_t)row * Hd + col) =
                        __floats2half2_rn(acc[ti][tj][0] + bv.x, acc[ti][tj][1] + bv.y);
                if (row + 8 < M)
                    *(__half2*)(C + (size_t)(row + 8) * Hd + col) =
                        __floats2half2_rn(acc[ti][tj][2] + bv.x, acc[ti][tj][3] + bv.y);
            }
        cur ^= 1;
        __syncthreads();                  // all reads of buf(cur^1) done before its refill next iter
    }
}

// ---------------- epilogue: gates -> h, c ----------------
__global__ void epilogue_kernel(float* __restrict__ outh, float* __restrict__ outc, int n4) {
    int stride = gridDim.x * blockDim.x;
    for (int i = blockIdx.x * blockDim.x + threadIdx.x; i < n4; i += stride) {
        size_t e = (size_t)i * 4;
        float4 wix = ld_half4(g_Wixh + e);
        float4 uih = ld_half4(g_Uihh + e);
        float4 wcx = ld_half4(g_Wcxh + e);
        float4 uch = ld_half4(g_Uchh + e);
        float4 wox = ld_half4(g_Woxh + e);
        float4 uoh = ld_half4(g_Uohh + e);
        float4 sf  = ((const float4*)g_sumfc)[i];

        float4 hc, cc;
        {
            float ig = sigm_f(wix.x + uih.x);
            float ct = tanh_f(wcx.x + uch.x);
            float cval = fmaf(ig, ct, sf.x);
            float og = sigm_f(wox.x + uoh.x);
            cc.x = cval; hc.x = og * tanh_f(cval);
        }
        {
            float ig = sigm_f(wix.y + uih.y);
            float ct = tanh_f(wcx.y + uch.y);
            float cval = fmaf(ig, ct, sf.y);
            float og = sigm_f(wox.y + uoh.y);
            cc.y = cval; hc.y = og * tanh_f(cval);
        }
        {
            float ig = sigm_f(wix.z + uih.z);
            float ct = tanh_f(wcx.z + uch.z);
            float cval = fmaf(ig, ct, sf.z);
            float og = sigm_f(wox.z + uoh.z);
            cc.z = cval; hc.z = og * tanh_f(cval);
        }
        {
            float ig = sigm_f(wix.w + uih.w);
            float ct = tanh_f(wcx.w + uch.w);
            float cval = fmaf(ig, ct, sf.w);
            float og = sigm_f(wox.w + uoh.w);
            cc.w = cval; hc.w = og * tanh_f(cval);
        }
        ((float4*)outh)[i] = hc;
        ((float4*)outc)[i] = cc;
    }
}

// ---------------- launch ----------------
extern "C" void kernel_launch(void* const* d_in, const int* in_sizes, int n_in,
                              void* d_out, int out_size) {
    const float* x_emb   = (const float*)d_in[0];
    const float* child_h = (const float*)d_in[1];
    const float* child_c = (const float*)d_in[2];
    const int*   ci      = (const int*)d_in[3];
    const int*   chi     = (const int*)d_in[4];
    const float* Wi_w = (const float*)d_in[5];
    const float* Ui_w = (const float*)d_in[6];
    const float* Wf_w = (const float*)d_in[7];
    const float* Uf_w = (const float*)d_in[8];
    const float* Wo_w = (const float*)d_in[9];
    const float* Uo_w = (const float*)d_in[10];
    const float* Wc_w = (const float*)d_in[11];
    const float* Uc_w = (const float*)d_in[12];
    const float* Wa_w = (const float*)d_in[13];
    const float* Ua_w = (const float*)d_in[14];
    const float* Wi_b = (const float*)d_in[15];
    const float* Wf_b = (const float*)d_in[16];
    const float* Wo_b = (const float*)d_in[17];
    const float* Wc_b = (const float*)d_in[18];
    const float* Wa_b = (const float*)d_in[19];
    const float* v_w  = (const float*)d_in[20];

    const int M = in_sizes[0] / Hd;
    const int L = in_sizes[3];

    float *p_hhat;
    cudaGetSymbolAddress((void**)&p_hhat, g_hhat);
    __half *p_Ahh, *p_Bxh, *p_Wfxh, *p_Ufhh, *p_Wixh, *p_Woxh, *p_Wcxh, *p_Uihh, *p_Uchh, *p_Uohh;
    cudaGetSymbolAddress((void**)&p_Ahh,  g_Ahh);
    cudaGetSymbolAddress((void**)&p_Bxh,  g_Bxh);
    cudaGetSymbolAddress((void**)&p_Wfxh, g_Wfxh);
    cudaGetSymbolAddress((void**)&p_Ufhh, g_Ufhh);
    cudaGetSymbolAddress((void**)&p_Wixh, g_Wixh);
    cudaGetSymbolAddress((void**)&p_Woxh, g_Woxh);
    cudaGetSymbolAddress((void**)&p_Wcxh, g_Wcxh);
    cudaGetSymbolAddress((void**)&p_Uihh, g_Uihh);
    cudaGetSymbolAddress((void**)&p_Uchh, g_Uchh);
    cudaGetSymbolAddress((void**)&p_Uohh, g_Uohh);
    char *p_wh;
    cudaGetSymbolAddress((void**)&p_wh, g_Wbh);

    float* outh = (float*)d_out;
    float* outc = outh + (size_t)M * Hd;

    const int mtiles = (M + 127) / 128;
    const int nblk = (MAXM + 1023) / 1024;

    cudaFuncSetAttribute(gemm_mma, cudaFuncAttributeMaxDynamicSharedMemorySize, S_TOT1);

    // weight order in g_Wbh: 0:Ua 1:Wi 2:Wf 3:Wo 4:Wc 5:Wa 6:Uf 7:Ui 8:Uc 9:Uo
    {
        PrepArgs pa;
        pa.W[0] = Ua_w; pa.W[1] = Wi_w; pa.W[2] = Wf_w; pa.W[3] = Wo_w; pa.W[4] = Wc_w;
        pa.W[5] = Wa_w; pa.W[6] = Uf_w; pa.W[7] = Ui_w; pa.W[8] = Uc_w; pa.W[9] = Uo_w;
        pa.child_h = child_h;
        pa.child_c = child_c;
        prep_kernel<<<296, 256>>>(pa, M);
    }

    // counting sort of pairs by ci
    hist_kernel<<<296, 256>>>(ci, L);
    scan1_kernel<<<nblk, 256>>>();
    scan2_kernel<<<1, 32>>>(nblk);
    fixup_kernel<<<64, 256>>>();
    scatter_kernel<<<296, 256>>>(ci, L);

    // phase 1: x-side (Bx, Wix, Wfx, Wox, Wcx) + child_h-side (Ah, Ufh), all fp16 out
    {
        TcArgs ga;
        ga.A1 = x_emb; ga.A2 = child_h; ga.nW1 = 5; ga.nW2 = 2; ga.M = M;
        int slot[7] = {0, 1, 2, 3, 4, 5, 6};
        const float* bs[7] = {nullptr, Wi_b, Wf_b, Wo_b, Wc_b, Wa_b, nullptr};
        __half* cs[7] = {p_Bxh, p_Wixh, p_Wfxh, p_Woxh, p_Wcxh, p_Ahh, p_Ufhh};
        for (int i = 0; i < 7; i++) {
            ga.wh[i] = p_wh + slot[i] * 32768;
            ga.b[i] = bs[i];
            ga.C[i] = cs[i];
        }
        gemm_mma<<<mtiles, NT, S_TOT1>>>(ga);
    }

    // fused segment kernel (replaces pair_e / pair_exp / pair_acc, no atomics)
    seg_kernel<<<(M + 7) / 8, 256>>>(chi, v_w, M);

    // phase 3: h_hat-side (Uih, Uch, Uoh), fp16 out
    {
        TcArgs ga;
        ga.A1 = p_hhat; ga.A2 = nullptr; ga.nW1 = 3; ga.nW2 = 0; ga.M = M;
        int slot[7] = {7, 8, 9, 7, 7, 7, 7};
        __half* cs[7] = {p_Uihh, p_Uchh, p_Uohh, p_Uihh, p_Uihh, p_Uihh, p_Uihh};
        for (int i = 0; i < 7; i++) {
            ga.wh[i] = p_wh + slot[i] * 32768;
            ga.b[i] = nullptr;
            ga.C[i] = cs[i];
        }
        gemm_mma<<<mtiles, NT, S_TOT1>>>(ga);
    }

    const int n4 = M * Hd / 4;
    epilogue_kernel<<<(n4 + 255) / 256, 256>>>(outh, outc, n4);
}

// round 15
// speedup vs baseline: 1.7196x; 1.1240x over previous
#include <cuda_runtime.h>
#include <cuda_fp16.h>
#include <cstdint>

#define Hd 128
#define MAXM 50048
#define MAXL 400128
#define SEPS 1e-9f
#define NT 512

// ---------------- scratch (device globals; no allocations) ----------------
__device__ float g_hhat[MAXM*Hd];
__device__ float g_sumfc[MAXM*Hd];
// fp16 GEMM outputs / pair operands
__device__ __half g_Ahh [MAXM*Hd];
__device__ __half g_Bxh [MAXM*Hd];
__device__ __half g_Wfxh[MAXM*Hd];
__device__ __half g_Ufhh[MAXM*Hd];
__device__ __half g_Wixh[MAXM*Hd];
__device__ __half g_Woxh[MAXM*Hd];
__device__ __half g_Wcxh[MAXM*Hd];
__device__ __half g_Uihh[MAXM*Hd];
__device__ __half g_Uchh[MAXM*Hd];
__device__ __half g_Uohh[MAXM*Hd];
__device__ __half g_chh [MAXM*Hd];   // fp16 shadow of child_h
__device__ __half g_cch [MAXM*Hd];   // fp16 shadow of child_c
// counting sort of pairs by ci
__device__ int g_cnt[MAXM];
__device__ int g_off[MAXM];
__device__ int g_cursor[MAXM];
__device__ int g_blk[64];
__device__ int g_sorted[MAXL];
// pre-swizzled single-fp16 weights: 10 x 128x128, 32KB each
__device__ __align__(16) char g_Wbh[10 * 32768];

// ---------------- scalar helpers ----------------
__device__ __forceinline__ float sigm_f(float x) {
    return __fdividef(1.0f, 1.0f + __expf(-x));
}
__device__ __forceinline__ float tanh_f(float x) {
    float e2 = __expf(2.0f * x);
    return 1.0f - __fdividef(2.0f, e2 + 1.0f);
}
__device__ __forceinline__ uint32_t smem_u32(const void* p) {
    uint32_t a;
    asm("{ .reg .u64 t; cvta.to.shared.u64 t, %1; cvt.u32.u64 %0, t; }" : "=r"(a) : "l"(p));
    return a;
}
__device__ __forceinline__ float4 ld_half4(const __half* p) {
    uint2 v = *(const uint2*)p;
    float2 lo = __half22float2(*(__half2*)&v.x);
    float2 hi = __half22float2(*(__half2*)&v.y);
    return make_float4(lo.x, lo.y, hi.x, hi.y);
}
__device__ __forceinline__ uint32_t packh2(float x, float y) {
    __half2 h = __floats2half2_rn(x, y);
    return *(uint32_t*)&h;
}

// ---------------- cp.async helpers ----------------
__device__ __forceinline__ void cpasync16(uint32_t saddr, const void* g) {
    asm volatile("cp.async.cg.shared.global [%0], [%1], 16;" :: "r"(saddr), "l"(g));
}
#define CP_COMMIT() asm volatile("cp.async.commit_group;" ::: "memory")
#define CP_WAIT0()  asm volatile("cp.async.wait_group 0;" ::: "memory")

// ---------------- mma / ldmatrix wrappers ----------------
__device__ __forceinline__ void ldm4(uint32_t* r, uint32_t addr) {
    asm volatile("ldmatrix.sync.aligned.m8n8.x4.shared.b16 {%0,%1,%2,%3}, [%4];"
                 : "=r"(r[0]), "=r"(r[1]), "=r"(r[2]), "=r"(r[3]) : "r"(addr));
}
__device__ __forceinline__ void mma16816h(float* d, const uint32_t* a, const uint32_t* b) {
    asm volatile("mma.sync.aligned.m16n8k16.row.col.f32.f16.f16.f32 "
                 "{%0,%1,%2,%3}, {%4,%5,%6,%7}, {%8,%9}, {%0,%1,%2,%3};"
                 : "+f"(d[0]), "+f"(d[1]), "+f"(d[2]), "+f"(d[3])
                 : "r"(a[0]), "r"(a[1]), "r"(a[2]), "r"(a[3]), "r"(b[0]), "r"(b[1]));
}

// swizzled byte offset of (row, colbyte) in a 128-row x 256B tile
__device__ __forceinline__ uint32_t swz(int row, int colbyte) {
    return (uint32_t)(row * 256 + (colbyte ^ ((row & 7) << 4)));
}

// ---------------- main-stream prep: fp16 weights only ----------------
struct PrepArgs { const float* W[10]; };

__global__ void prep_w_kernel(PrepArgs pa) {
    int stride = gridDim.x * blockDim.x;
    int gt = blockIdx.x * blockDim.x + threadIdx.x;
    for (int idx = gt; idx < 10 * 8192; idx += stride) {
        int w = idx >> 13;
        int i = idx & 8191;
        int row = i >> 6;
        int c2 = i & 63;
        float2 v = *(const float2*)(pa.W[w] + (size_t)row * Hd + c2 * 2);
        *(uint32_t*)(g_Wbh + w * 32768 + swz(row, c2 * 4)) = packh2(v.x, v.y);
    }
}

// ---------------- side-stream: zero counters + fp16 shadows ----------------
__global__ void side_kernel(const float* __restrict__ child_h,
                            const float* __restrict__ child_c, int M) {
    int stride = gridDim.x * blockDim.x;
    int gt = blockIdx.x * blockDim.x + threadIdx.x;
    for (int i = gt; i < MAXM; i += stride) g_cnt[i] = 0;
    int n2 = M * Hd / 2;
    for (int i = gt; i < n2; i += stride) {
        float2 vh = ((const float2*)child_h)[i];
        float2 vc = ((const float2*)child_c)[i];
        ((__half2*)g_chh)[i] = __floats2half2_rn(vh.x, vh.y);
        ((__half2*)g_cch)[i] = __floats2half2_rn(vc.x, vc.y);
    }
}

// ---------------- counting sort of pairs by ci ----------------
__global__ void hist_kernel(const int* __restrict__ ci, int L) {
    int stride = gridDim.x * blockDim.x;
    for (int l = blockIdx.x * blockDim.x + threadIdx.x; l < L; l += stride)
        atomicAdd(&g_cnt[ci[l]], 1);
}

// per-1024-block exclusive scan; 256 threads, 4 elems/thread
__global__ void scan1_kernel() {
    __shared__ int warp_tot[8];
    __shared__ int warp_off[8];
    int t = threadIdx.x;
    int lane = t & 31;
    int wid = t >> 5;
    int base = blockIdx.x * 1024 + t * 4;
    int v0 = base + 0 < MAXM ? g_cnt[base + 0] : 0;
    int v1 = base + 1 < MAXM ? g_cnt[base + 1] : 0;
    int v2 = base + 2 < MAXM ? g_cnt[base + 2] : 0;
    int v3 = base + 3 < MAXM ? g_cnt[base + 3] : 0;
    int p1 = v0, p2 = v0 + v1, p3 = v0 + v1 + v2;
    int tsum = p3 + v3;
    int x = tsum;
#pragma unroll
    for (int o = 1; o < 32; o <<= 1) {
        int y = __shfl_up_sync(0xFFFFFFFFu, x, o);
        if (lane >= o) x += y;
    }
    if (lane == 31) warp_tot[wid] = x;
    __syncthreads();
    if (t == 0) {
        int r = 0;
#pragma unroll
        for (int i = 0; i < 8; i++) { warp_off[i] = r; r += warp_tot[i]; }
        g_blk[blockIdx.x] = r;
    }
    __syncthreads();
    int excl = x - tsum + warp_off[wid];
    if (base + 0 < MAXM) g_off[base + 0] = excl;
    if (base + 1 < MAXM) g_off[base + 1] = excl + p1;
    if (base + 2 < MAXM) g_off[base + 2] = excl + p2;
    if (base + 3 < MAXM) g_off[base + 3] = excl + p3;
}

// parallel scan of block totals (single warp, 64 lanes-worth handled by 2 elems/lane)
__global__ void scan2_kernel(int nblk) {
    int lane = threadIdx.x;
    int v0 = lane * 2 + 0 < nblk ? g_blk[lane * 2 + 0] : 0;
    int v1 = lane * 2 + 1 < nblk ? g_blk[lane * 2 + 1] : 0;
    int tsum = v0 + v1;
    int x = tsum;
#pragma unroll
    for (int o = 1; o < 32; o <<= 1) {
        int y = __shfl_up_sync(0xFFFFFFFFu, x, o);
        if (lane >= o) x += y;
    }
    int excl = x - tsum;
    if (lane * 2 + 0 < nblk) g_blk[lane * 2 + 0] = excl;
    if (lane * 2 + 1 < nblk) g_blk[lane * 2 + 1] = excl + v0;
}

__global__ void fixup_kernel() {
    int stride = gridDim.x * blockDim.x;
    for (int i = blockIdx.x * blockDim.x + threadIdx.x; i < MAXM; i += stride) {
        int o = g_off[i] + g_blk[i >> 10];
        g_off[i] = o;
        g_cursor[i] = o;
    }
}

__global__ void scatter_kernel(const int* __restrict__ ci, int L) {
    int stride = gridDim.x * blockDim.x;
    for (int l = blockIdx.x * blockDim.x + threadIdx.x; l < L; l += stride) {
        int pos = atomicAdd(&g_cursor[ci[l]], 1);
        g_sorted[pos] = l;
    }
}

// ---------------- fused segment kernel: softmax attention + forget gate ----------------
__global__ void seg_kernel(const int* __restrict__ chi, const float* __restrict__ v,
                           int M) {
    __shared__ float vs[Hd];
    if (threadIdx.x < Hd) vs[threadIdx.x] = v[threadIdx.x];
    __syncthreads();

    int m = blockIdx.x * (blockDim.x >> 5) + (threadIdx.x >> 5);
    int lane = threadIdx.x & 31;
    if (m >= M) return;

    int start = __ldg(g_off + m);
    int end   = __ldg(g_cursor + m);   // after scatter, cursor == segment end

    size_t mo = (size_t)m * Hd + lane * 4;
    float4 vv = *(const float4*)(vs + lane * 4);
    float4 bx = ld_half4(g_Bxh + mo);
    float4 wf = ld_half4(g_Wfxh + mo);

    float runm = -3.4e38f, s = 0.f;
    float4 acch = make_float4(0.f, 0.f, 0.f, 0.f);
    float4 accf = make_float4(0.f, 0.f, 0.f, 0.f);

    for (int p = start; p < end; p++) {
        int l = __ldg(g_sorted + p);
        int ch = __ldg(chi + l);
        size_t cho = (size_t)ch * Hd + lane * 4;

        float4 a = ld_half4(g_Ahh + cho);
        float e = tanh_f(a.x + bx.x) * vv.x + tanh_f(a.y + bx.y) * vv.y +
                  tanh_f(a.z + bx.z) * vv.z + tanh_f(a.w + bx.w) * vv.w;
#pragma unroll
        for (int o = 16; o; o >>= 1) e += __shfl_xor_sync(0xFFFFFFFFu, e, o);

        float mnew = fmaxf(runm, e);
        float scale = __expf(runm - mnew);   // 0 on first pair (runm = -big)
        float xe = __expf(e - mnew);
        s = s * scale + xe;

        float4 hv = ld_half4(g_chh + cho);
        acch.x = acch.x * scale + xe * hv.x;
        acch.y = acch.y * scale + xe * hv.y;
        acch.z = acch.z * scale + xe * hv.z;
        acch.w = acch.w * scale + xe * hv.w;

        float4 uf = ld_half4(g_Ufhh + cho);
        float4 cv = ld_half4(g_cch + cho);
        accf.x += sigm_f(wf.x + uf.x) * cv.x;
        accf.y += sigm_f(wf.y + uf.y) * cv.y;
        accf.z += sigm_f(wf.z + uf.z) * cv.z;
        accf.w += sigm_f(wf.w + uf.w) * cv.w;

        runm = mnew;
    }

    float inv = __fdividef(1.0f, s + SEPS);
    float4 hh = make_float4(acch.x * inv, acch.y * inv, acch.z * inv, acch.w * inv);
    *(float4*)(g_hhat + mo)  = hh;
    *(float4*)(g_sumfc + mo) = accf;
}

// ---------------- shared GEMM building blocks ----------------
#define SA    0
#define SW0   32768
#define S_TOT1 (32768 * 3)

__device__ __forceinline__ void conv_tile(const float* __restrict__ A, int m0, int M,
                                          char* dst, int tid) {
#pragma unroll
    for (int it = 0; it < 8192 / NT; it++) {
        int i = tid + it * NT;
        int row = i >> 6;
        int c2 = i & 63;
        float2 v = make_float2(0.f, 0.f);
        if (m0 + row < M) v = *(const float2*)(A + (size_t)(m0 + row) * Hd + c2 * 2);
        *(uint32_t*)(dst + swz(row, c2 * 4)) = packh2(v.x, v.y);
    }
}

// async fetch of one 32KB weight tile into smem buffer
__device__ __forceinline__ void prefetch_w(uint32_t sbuf, const char* wh, int tid) {
#pragma unroll
    for (int it = 0; it < 2048 / NT; it++) {
        int i = tid + it * NT;
        cpasync16(sbuf + i * 16, wh + i * 16);
    }
    CP_COMMIT();
}

// compute 128x128 fp16 gemm tile into acc[2][4][4]
__device__ __forceinline__ void gemm_core(const uint32_t smb, uint32_t swoff,
                                          float acc[2][4][4],
                                          int arow0, int akb, int brow0, int bkb) {
#pragma unroll
    for (int ti = 0; ti < 2; ti++)
#pragma unroll
        for (int tj = 0; tj < 4; tj++)
#pragma unroll
            for (int k = 0; k < 4; k++) acc[ti][tj][k] = 0.f;

#pragma unroll
    for (int ks = 0; ks < 8; ks++) {
        const int kb0 = ks * 32;
        uint32_t ah[2][4], bh[2][4];
#pragma unroll
        for (int ti = 0; ti < 2; ti++) {
            int row = arow0 + ti * 16;
            ldm4(ah[ti], smb + SA + swz(row, kb0 + akb));
        }
#pragma unroll
        for (int tp = 0; tp < 2; tp++) {
            int row = brow0 + tp * 16;
            ldm4(bh[tp], smb + swoff + swz(row, kb0 + bkb));
        }
#pragma unroll
        for (int ti = 0; ti < 2; ti++)
#pragma unroll
            for (int tj = 0; tj < 4; tj++) {
                const uint32_t* bp = &bh[tj >> 1][(tj & 1) * 2];
                mma16816h(acc[ti][tj], ah[ti], bp);
            }
    }
}

// ---------------- batched GEMM: fp16 outputs, double-buffered weights ----------------
struct TcArgs {
    const float* A1;
    const float* A2;
    const char* wh[7];
    const float* b[7];
    __half* C[7];
    int nW1, nW2, M;
};

__global__ void __launch_bounds__(NT, 1) gemm_mma(TcArgs ga) {
    extern __shared__ char sm[];
    const uint32_t smb = smem_u32(sm);
    const int tid = threadIdx.x;
    const int wid = tid >> 5;
    const int lane = tid & 31;
    const int m0 = blockIdx.x * 128;
    const int M = ga.M;
    const int wm = wid >> 2;
    const int wn = wid & 3;
    const int sub = lane & 7;
    const int quad = lane >> 3;
    const int arow0 = wm * 32 + sub + (quad & 1) * 8;
    const int akb   = (quad >> 1) * 16;
    const int brow0 = wn * 32 + sub + (quad >> 1) * 8;
    const int bkb   = (quad & 1) * 16;
    const int g = lane >> 2;
    const int tg = lane & 3;

    const int nWtot = ga.nW1 + ga.nW2;

    // prologue: async-fetch weight 0, convert first A tile
    prefetch_w(smb + SW0, ga.wh[0], tid);
    conv_tile(ga.A1, m0, M, sm + SA, tid);

    int cur = 0;
    for (int w = 0; w < nWtot; w++) {
        CP_WAIT0();
        __syncthreads();                  // weight buf(cur) + A tile visible

        if (w == ga.nW1) {
            // switch A operand to A2 (prior gemm readers of SA passed the sync)
            conv_tile(ga.A2, m0, M, sm + SA, tid);
        }
        if (w + 1 < nWtot)
            prefetch_w(smb + SW0 + (cur ^ 1) * 32768, ga.wh[w + 1], tid);
        if (w == ga.nW1)
            __syncthreads();              // new A tile visible

        float acc[2][4][4];
        gemm_core(smb, SW0 + cur * 32768, acc, arow0, akb, brow0, bkb);

        // store fp16 C tile (+bias via __ldg; bias is 512B, L2-broadcast)
        const float* bias = ga.b[w];
        __half* __restrict__ C = ga.C[w];
#pragma unroll
        for (int ti = 0; ti < 2; ti++)
#pragma unroll
            for (int tj = 0; tj < 4; tj++) {
                int row = m0 + wm * 32 + ti * 16 + g;
                int col = wn * 32 + tj * 8 + tg * 2;
                float2 bv = bias ? *(const float2*)(bias + col) : make_float2(0.f, 0.f);
                if (row < M)
                    *(__half2*)(C + (size_t)row * Hd + col) =
                        __floats2half2_rn(acc[ti][tj][0] + bv.x, acc[ti][tj][1] + bv.y);
                if (row + 8 < M)
                    *(__half2*)(C + (size_t)(row + 8) * Hd + col) =
                        __floats2half2_rn(acc[ti][tj][2] + bv.x, acc[ti][tj][3] + bv.y);
            }
        cur ^= 1;
        __syncthreads();                  // all reads of buf(cur^1) done before its refill next iter
    }
}

// ---------------- epilogue: gates -> h, c ----------------
__global__ void epilogue_kernel(float* __restrict__ outh, float* __restrict__ outc, int n4) {
    int stride = gridDim.x * blockDim.x;
    for (int i = blockIdx.x * blockDim.x + threadIdx.x; i < n4; i += stride) {
        size_t e = (size_t)i * 4;
        float4 wix = ld_half4(g_Wixh + e);
        float4 uih = ld_half4(g_Uihh + e);
        float4 wcx = ld_half4(g_Wcxh + e);
        float4 uch = ld_half4(g_Uchh + e);
        float4 wox = ld_half4(g_Woxh + e);
        float4 uoh = ld_half4(g_Uohh + e);
        float4 sf  = ((const float4*)g_sumfc)[i];

        float4 hc, cc;
        {
            float ig = sigm_f(wix.x + uih.x);
            float ct = tanh_f(wcx.x + uch.x);
            float cval = fmaf(ig, ct, sf.x);
            float og = sigm_f(wox.x + uoh.x);
            cc.x = cval; hc.x = og * tanh_f(cval);
        }
        {
            float ig = sigm_f(wix.y + uih.y);
            float ct = tanh_f(wcx.y + uch.y);
            float cval = fmaf(ig, ct, sf.y);
            float og = sigm_f(wox.y + uoh.y);
            cc.y = cval; hc.y = og * tanh_f(cval);
        }
        {
            float ig = sigm_f(wix.z + uih.z);
            float ct = tanh_f(wcx.z + uch.z);
            float cval = fmaf(ig, ct, sf.z);
            float og = sigm_f(wox.z + uoh.z);
            cc.z = cval; hc.z = og * tanh_f(cval);
        }
        {
            float ig = sigm_f(wix.w + uih.w);
            float ct = tanh_f(wcx.w + uch.w);
            float cval = fmaf(ig, ct, sf.w);
            float og = sigm_f(wox.w + uoh.w);
            cc.w = cval; hc.w = og * tanh_f(cval);
        }
        ((float4*)outh)[i] = hc;
        ((float4*)outc)[i] = cc;
    }
}

// ---------------- launch ----------------
extern "C" void kernel_launch(void* const* d_in, const int* in_sizes, int n_in,
                              void* d_out, int out_size) {
    const float* x_emb   = (const float*)d_in[0];
    const float* child_h = (const float*)d_in[1];
    const float* child_c = (const float*)d_in[2];
    const int*   ci      = (const int*)d_in[3];
    const int*   chi     = (const int*)d_in[4];
    const float* Wi_w = (const float*)d_in[5];
    const float* Ui_w = (const float*)d_in[6];
    const float* Wf_w = (const float*)d_in[7];
    const float* Uf_w = (const float*)d_in[8];
    const float* Wo_w = (const float*)d_in[9];
    const float* Uo_w = (const float*)d_in[10];
    const float* Wc_w = (const float*)d_in[11];
    const float* Uc_w = (const float*)d_in[12];
    const float* Wa_w = (const float*)d_in[13];
    const float* Ua_w = (const float*)d_in[14];
    const float* Wi_b = (const float*)d_in[15];
    const float* Wf_b = (const float*)d_in[16];
    const float* Wo_b = (const float*)d_in[17];
    const float* Wc_b = (const float*)d_in[18];
    const float* Wa_b = (const float*)d_in[19];
    const float* v_w  = (const float*)d_in[20];

    const int M = in_sizes[0] / Hd;
    const int L = in_sizes[3];

    float *p_hhat;
    cudaGetSymbolAddress((void**)&p_hhat, g_hhat);
    __half *p_Ahh, *p_Bxh, *p_Wfxh, *p_Ufhh, *p_Wixh, *p_Woxh, *p_Wcxh, *p_Uihh, *p_Uchh, *p_Uohh;
    cudaGetSymbolAddress((void**)&p_Ahh,  g_Ahh);
    cudaGetSymbolAddress((void**)&p_Bxh,  g_Bxh);
    cudaGetSymbolAddress((void**)&p_Wfxh, g_Wfxh);
    cudaGetSymbolAddress((void**)&p_Ufhh, g_Ufhh);
    cudaGetSymbolAddress((void**)&p_Wixh, g_Wixh);
    cudaGetSymbolAddress((void**)&p_Woxh, g_Woxh);
    cudaGetSymbolAddress((void**)&p_Wcxh, g_Wcxh);
    cudaGetSymbolAddress((void**)&p_Uihh, g_Uihh);
    cudaGetSymbolAddress((void**)&p_Uchh, g_Uchh);
    cudaGetSymbolAddress((void**)&p_Uohh, g_Uohh);
    char *p_wh;
    cudaGetSymbolAddress((void**)&p_wh, g_Wbh);

    float* outh = (float*)d_out;
    float* outc = outh + (size_t)M * Hd;

    const int mtiles = (M + 127) / 128;
    const int nblk = (MAXM + 1023) / 1024;

    cudaFuncSetAttribute(gemm_mma, cudaFuncAttributeMaxDynamicSharedMemorySize, S_TOT1);

    // one-time side stream + fork/join events (host resources; identical work per call)
    static cudaStream_t s2 = nullptr;
    static cudaEvent_t evF = nullptr, evJ = nullptr;
    if (!s2) {
        cudaStreamCreateWithFlags(&s2, cudaStreamNonBlocking);
        cudaEventCreateWithFlags(&evF, cudaEventDisableTiming);
        cudaEventCreateWithFlags(&evJ, cudaEventDisableTiming);
    }

    // fork: side stream does shadows + counting sort, overlapping main GEMM1
    cudaEventRecord(evF, 0);
    cudaStreamWaitEvent(s2, evF, 0);
    side_kernel<<<296, 256, 0, s2>>>(child_h, child_c, M);
    hist_kernel<<<296, 256, 0, s2>>>(ci, L);
    scan1_kernel<<<nblk, 256, 0, s2>>>();
    scan2_kernel<<<1, 32, 0, s2>>>(nblk);
    fixup_kernel<<<64, 256, 0, s2>>>();
    scatter_kernel<<<296, 256, 0, s2>>>(ci, L);
    cudaEventRecord(evJ, s2);

    // main stream: weights prep + phase-1 GEMMs
    {
        PrepArgs pa;
        pa.W[0] = Ua_w; pa.W[1] = Wi_w; pa.W[2] = Wf_w; pa.W[3] = Wo_w; pa.W[4] = Wc_w;
        pa.W[5] = Wa_w; pa.W[6] = Uf_w; pa.W[7] = Ui_w; pa.W[8] = Uc_w; pa.W[9] = Uo_w;
        prep_w_kernel<<<148, 256>>>(pa);
    }
    {
        TcArgs ga;
        ga.A1 = x_emb; ga.A2 = child_h; ga.nW1 = 5; ga.nW2 = 2; ga.M = M;
        int slot[7] = {0, 1, 2, 3, 4, 5, 6};
        const float* bs[7] = {nullptr, Wi_b, Wf_b, Wo_b, Wc_b, Wa_b, nullptr};
        __half* cs[7] = {p_Bxh, p_Wixh, p_Wfxh, p_Woxh, p_Wcxh, p_Ahh, p_Ufhh};
        for (int i = 0; i < 7; i++) {
            ga.wh[i] = p_wh + slot[i] * 32768;
            ga.b[i] = bs[i];
            ga.C[i] = cs[i];
        }
        gemm_mma<<<mtiles, NT, S_TOT1>>>(ga);
    }

    // join: seg needs sorted pairs + shadows + GEMM1 outputs
    cudaStreamWaitEvent(0, evJ, 0);
    seg_kernel<<<(M + 7) / 8, 256>>>(chi, v_w, M);

    // phase 3: h_hat-side (Uih, Uch, Uoh), fp16 out
    {
        TcArgs ga;
        ga.A1 = p_hhat; ga.A2 = nullptr; ga.nW1 = 3; ga.nW2 = 0; ga.M = M;
        int slot[7] = {7, 8, 9, 7, 7, 7, 7};
        __half* cs[7] = {p_Uihh, p_Uchh, p_Uohh, p_Uihh, p_Uihh, p_Uihh, p_Uihh};
        for (int i = 0; i < 7; i++) {
            ga.wh[i] = p_wh + slot[i] * 32768;
            ga.b[i] = nullptr;
            ga.C[i] = cs[i];
        }
        gemm_mma<<<mtiles, NT, S_TOT1>>>(ga);
    }

    const int n4 = M * Hd / 4;
    epilogue_kernel<<<(n4 + 255) / 256, 256>>>(outh, outc, n4);
}

// round 16
// speedup vs baseline: 1.8450x; 1.0729x over previous
#include <cuda_runtime.h>
#include <cuda_fp16.h>
#include <cstdint>

#define Hd 128
#define MAXM 50048
#define MAXL 400128
#define SEPS 1e-9f
#define NT 512

// ---------------- scratch (device globals; no allocations) ----------------
__device__ float g_hhat[MAXM*Hd];
__device__ float g_sumfc[MAXM*Hd];
// fp16 GEMM outputs / pair operands
__device__ __half g_Ahh [MAXM*Hd];
__device__ __half g_Bxh [MAXM*Hd];
__device__ __half g_Wfxh[MAXM*Hd];
__device__ __half g_Ufhh[MAXM*Hd];
__device__ __half g_Wixh[MAXM*Hd];
__device__ __half g_Woxh[MAXM*Hd];
__device__ __half g_Wcxh[MAXM*Hd];
__device__ __half g_Uihh[MAXM*Hd];
__device__ __half g_Uchh[MAXM*Hd];
__device__ __half g_Uohh[MAXM*Hd];
__device__ __half g_chh [MAXM*Hd];   // fp16 shadow of child_h
__device__ __half g_cch [MAXM*Hd];   // fp16 shadow of child_c
// counting sort of pairs by ci
__device__ int g_cnt[MAXM];
__device__ int g_off[MAXM];
__device__ int g_cursor[MAXM];
__device__ int g_blk[64];
__device__ int g_sorted[MAXL];
// pre-swizzled single-fp16 weights: 10 x 128x128, 32KB each
__device__ __align__(16) char g_Wbh[10 * 32768];

// ---------------- scalar helpers ----------------
__device__ __forceinline__ float sigm_f(float x) {
    return __fdividef(1.0f, 1.0f + __expf(-x));
}
__device__ __forceinline__ float tanh_f(float x) {
    float e2 = __expf(2.0f * x);
    return 1.0f - __fdividef(2.0f, e2 + 1.0f);
}
__device__ __forceinline__ uint32_t smem_u32(const void* p) {
    uint32_t a;
    asm("{ .reg .u64 t; cvta.to.shared.u64 t, %1; cvt.u32.u64 %0, t; }" : "=r"(a) : "l"(p));
    return a;
}
__device__ __forceinline__ float4 ld_half4(const __half* p) {
    uint2 v = *(const uint2*)p;
    float2 lo = __half22float2(*(__half2*)&v.x);
    float2 hi = __half22float2(*(__half2*)&v.y);
    return make_float4(lo.x, lo.y, hi.x, hi.y);
}
__device__ __forceinline__ uint32_t packh2(float x, float y) {
    __half2 h = __floats2half2_rn(x, y);
    return *(uint32_t*)&h;
}

// ---------------- cp.async helpers ----------------
__device__ __forceinline__ void cpasync16(uint32_t saddr, const void* g) {
    asm volatile("cp.async.cg.shared.global [%0], [%1], 16;" :: "r"(saddr), "l"(g));
}
#define CP_COMMIT() asm volatile("cp.async.commit_group;" ::: "memory")
#define CP_WAIT0()  asm volatile("cp.async.wait_group 0;" ::: "memory")

// ---------------- mma / ldmatrix wrappers ----------------
__device__ __forceinline__ void ldm4(uint32_t* r, uint32_t addr) {
    asm volatile("ldmatrix.sync.aligned.m8n8.x4.shared.b16 {%0,%1,%2,%3}, [%4];"
                 : "=r"(r[0]), "=r"(r[1]), "=r"(r[2]), "=r"(r[3]) : "r"(addr));
}
__device__ __forceinline__ void mma16816h(float* d, const uint32_t* a, const uint32_t* b) {
    asm volatile("mma.sync.aligned.m16n8k16.row.col.f32.f16.f16.f32 "
                 "{%0,%1,%2,%3}, {%4,%5,%6,%7}, {%8,%9}, {%0,%1,%2,%3};"
                 : "+f"(d[0]), "+f"(d[1]), "+f"(d[2]), "+f"(d[3])
                 : "r"(a[0]), "r"(a[1]), "r"(a[2]), "r"(a[3]), "r"(b[0]), "r"(b[1]));
}

// swizzled byte offset of (row, colbyte) in a 128-row x 256B tile
__device__ __forceinline__ uint32_t swz(int row, int colbyte) {
    return (uint32_t)(row * 256 + (colbyte ^ ((row & 7) << 4)));
}

// ---------------- main-stream prep: fp16 weights only ----------------
struct PrepArgs { const float* W[10]; };

__global__ void prep_w_kernel(PrepArgs pa) {
    int stride = gridDim.x * blockDim.x;
    int gt = blockIdx.x * blockDim.x + threadIdx.x;
    for (int idx = gt; idx < 10 * 8192; idx += stride) {
        int w = idx >> 13;
        int i = idx & 8191;
        int row = i >> 6;
        int c2 = i & 63;
        float2 v = *(const float2*)(pa.W[w] + (size_t)row * Hd + c2 * 2);
        *(uint32_t*)(g_Wbh + w * 32768 + swz(row, c2 * 4)) = packh2(v.x, v.y);
    }
}

// ---------------- side-stream: zero counters + fp16 shadows ----------------
__global__ void side_kernel(const float* __restrict__ child_h,
                            const float* __restrict__ child_c, int M) {
    int stride = gridDim.x * blockDim.x;
    int gt = blockIdx.x * blockDim.x + threadIdx.x;
    for (int i = gt; i < MAXM; i += stride) g_cnt[i] = 0;
    int n2 = M * Hd / 2;
    for (int i = gt; i < n2; i += stride) {
        float2 vh = ((const float2*)child_h)[i];
        float2 vc = ((const float2*)child_c)[i];
        ((__half2*)g_chh)[i] = __floats2half2_rn(vh.x, vh.y);
        ((__half2*)g_cch)[i] = __floats2half2_rn(vc.x, vc.y);
    }
}

// ---------------- counting sort of pairs by ci ----------------
__global__ void hist_kernel(const int* __restrict__ ci, int L) {
    int stride = gridDim.x * blockDim.x;
    for (int l = blockIdx.x * blockDim.x + threadIdx.x; l < L; l += stride)
        atomicAdd(&g_cnt[ci[l]], 1);
}

// per-1024-block exclusive scan; 256 threads, 4 elems/thread
__global__ void scan1_kernel() {
    __shared__ int warp_tot[8];
    __shared__ int warp_off[8];
    int t = threadIdx.x;
    int lane = t & 31;
    int wid = t >> 5;
    int base = blockIdx.x * 1024 + t * 4;
    int v0 = base + 0 < MAXM ? g_cnt[base + 0] : 0;
    int v1 = base + 1 < MAXM ? g_cnt[base + 1] : 0;
    int v2 = base + 2 < MAXM ? g_cnt[base + 2] : 0;
    int v3 = base + 3 < MAXM ? g_cnt[base + 3] : 0;
    int p1 = v0, p2 = v0 + v1, p3 = v0 + v1 + v2;
    int tsum = p3 + v3;
    int x = tsum;
#pragma unroll
    for (int o = 1; o < 32; o <<= 1) {
        int y = __shfl_up_sync(0xFFFFFFFFu, x, o);
        if (lane >= o) x += y;
    }
    if (lane == 31) warp_tot[wid] = x;
    __syncthreads();
    if (t == 0) {
        int r = 0;
#pragma unroll
        for (int i = 0; i < 8; i++) { warp_off[i] = r; r += warp_tot[i]; }
        g_blk[blockIdx.x] = r;
    }
    __syncthreads();
    int excl = x - tsum + warp_off[wid];
    if (base + 0 < MAXM) g_off[base + 0] = excl;
    if (base + 1 < MAXM) g_off[base + 1] = excl + p1;
    if (base + 2 < MAXM) g_off[base + 2] = excl + p2;
    if (base + 3 < MAXM) g_off[base + 3] = excl + p3;
}

// parallel scan of block totals (single warp, 2 elems/lane)
__global__ void scan2_kernel(int nblk) {
    int lane = threadIdx.x;
    int v0 = lane * 2 + 0 < nblk ? g_blk[lane * 2 + 0] : 0;
    int v1 = lane * 2 + 1 < nblk ? g_blk[lane * 2 + 1] : 0;
    int tsum = v0 + v1;
    int x = tsum;
#pragma unroll
    for (int o = 1; o < 32; o <<= 1) {
        int y = __shfl_up_sync(0xFFFFFFFFu, x, o);
        if (lane >= o) x += y;
    }
    int excl = x - tsum;
    if (lane * 2 + 0 < nblk) g_blk[lane * 2 + 0] = excl;
    if (lane * 2 + 1 < nblk) g_blk[lane * 2 + 1] = excl + v0;
}

__global__ void fixup_kernel() {
    int stride = gridDim.x * blockDim.x;
    for (int i = blockIdx.x * blockDim.x + threadIdx.x; i < MAXM; i += stride) {
        int o = g_off[i] + g_blk[i >> 10];
        g_off[i] = o;
        g_cursor[i] = o;
    }
}

__global__ void scatter_kernel(const int* __restrict__ ci, int L) {
    int stride = gridDim.x * blockDim.x;
    for (int l = blockIdx.x * blockDim.x + threadIdx.x; l < L; l += stride) {
        int pos = atomicAdd(&g_cursor[ci[l]], 1);
        g_sorted[pos] = l;
    }
}

// ---------------- seg_attn: online-softmax attention -> h_hat ----------------
__global__ void seg_attn_kernel(const int* __restrict__ chi, const float* __restrict__ v,
                                int M) {
    __shared__ float vs[Hd];
    if (threadIdx.x < Hd) vs[threadIdx.x] = v[threadIdx.x];
    __syncthreads();

    int m = blockIdx.x * (blockDim.x >> 5) + (threadIdx.x >> 5);
    int lane = threadIdx.x & 31;
    if (m >= M) return;

    int start = __ldg(g_off + m);
    int end   = __ldg(g_cursor + m);   // after scatter, cursor == segment end

    size_t mo = (size_t)m * Hd + lane * 4;
    float4 vv = *(const float4*)(vs + lane * 4);
    float4 bx = ld_half4(g_Bxh + mo);

    float runm = -3.4e38f, s = 0.f;
    float4 acch = make_float4(0.f, 0.f, 0.f, 0.f);

    for (int p = start; p < end; p++) {
        int l = __ldg(g_sorted + p);
        int ch = __ldg(chi + l);
        size_t cho = (size_t)ch * Hd + lane * 4;

        float4 a = ld_half4(g_Ahh + cho);
        float e = tanh_f(a.x + bx.x) * vv.x + tanh_f(a.y + bx.y) * vv.y +
                  tanh_f(a.z + bx.z) * vv.z + tanh_f(a.w + bx.w) * vv.w;
#pragma unroll
        for (int o = 16; o; o >>= 1) e += __shfl_xor_sync(0xFFFFFFFFu, e, o);

        float mnew = fmaxf(runm, e);
        float scale = __expf(runm - mnew);   // 0 on first pair (runm = -big)
        float xe = __expf(e - mnew);
        s = s * scale + xe;

        float4 hv = ld_half4(g_chh + cho);
        acch.x = acch.x * scale + xe * hv.x;
        acch.y = acch.y * scale + xe * hv.y;
        acch.z = acch.z * scale + xe * hv.z;
        acch.w = acch.w * scale + xe * hv.w;

        runm = mnew;
    }

    float inv = __fdividef(1.0f, s + SEPS);
    *(float4*)(g_hhat + mo) =
        make_float4(acch.x * inv, acch.y * inv, acch.z * inv, acch.w * inv);
}

// ---------------- seg_forget: forget-gate accumulation -> sumfc ----------------
__global__ void seg_forget_kernel(const int* __restrict__ chi, int M) {
    int m = blockIdx.x * (blockDim.x >> 5) + (threadIdx.x >> 5);
    int lane = threadIdx.x & 31;
    if (m >= M) return;

    int start = __ldg(g_off + m);
    int end   = __ldg(g_cursor + m);

    size_t mo = (size_t)m * Hd + lane * 4;
    float4 wf = ld_half4(g_Wfxh + mo);
    float4 accf = make_float4(0.f, 0.f, 0.f, 0.f);

    for (int p = start; p < end; p++) {
        int l = __ldg(g_sorted + p);
        int ch = __ldg(chi + l);
        size_t cho = (size_t)ch * Hd + lane * 4;

        float4 uf = ld_half4(g_Ufhh + cho);
        float4 cv = ld_half4(g_cch + cho);
        accf.x += sigm_f(wf.x + uf.x) * cv.x;
        accf.y += sigm_f(wf.y + uf.y) * cv.y;
        accf.z += sigm_f(wf.z + uf.z) * cv.z;
        accf.w += sigm_f(wf.w + uf.w) * cv.w;
    }
    *(float4*)(g_sumfc + mo) = accf;
}

// ---------------- shared GEMM building blocks ----------------
#define SA    0
#define SW0   32768
#define S_TOT1 (32768 * 3)

__device__ __forceinline__ void conv_tile(const float* __restrict__ A, int m0, int M,
                                          char* dst, int tid) {
#pragma unroll
    for (int it = 0; it < 8192 / NT; it++) {
        int i = tid + it * NT;
        int row = i >> 6;
        int c2 = i & 63;
        float2 v = make_float2(0.f, 0.f);
        if (m0 + row < M) v = *(const float2*)(A + (size_t)(m0 + row) * Hd + c2 * 2);
        *(uint32_t*)(dst + swz(row, c2 * 4)) = packh2(v.x, v.y);
    }
}

// async fetch of one 32KB weight tile into smem buffer
__device__ __forceinline__ void prefetch_w(uint32_t sbuf, const char* wh, int tid) {
#pragma unroll
    for (int it = 0; it < 2048 / NT; it++) {
        int i = tid + it * NT;
        cpasync16(sbuf + i * 16, wh + i * 16);
    }
    CP_COMMIT();
}

// compute 128x128 fp16 gemm tile into acc[2][4][4]
__device__ __forceinline__ void gemm_core(const uint32_t smb, uint32_t swoff,
                                          float acc[2][4][4],
                                          int arow0, int akb, int brow0, int bkb) {
#pragma unroll
    for (int ti = 0; ti < 2; ti++)
#pragma unroll
        for (int tj = 0; tj < 4; tj++)
#pragma unroll
            for (int k = 0; k < 4; k++) acc[ti][tj][k] = 0.f;

#pragma unroll
    for (int ks = 0; ks < 8; ks++) {
        const int kb0 = ks * 32;
        uint32_t ah[2][4], bh[2][4];
#pragma unroll
        for (int ti = 0; ti < 2; ti++) {
            int row = arow0 + ti * 16;
            ldm4(ah[ti], smb + SA + swz(row, kb0 + akb));
        }
#pragma unroll
        for (int tp = 0; tp < 2; tp++) {
            int row = brow0 + tp * 16;
            ldm4(bh[tp], smb + swoff + swz(row, kb0 + bkb));
        }
#pragma unroll
        for (int ti = 0; ti < 2; ti++)
#pragma unroll
            for (int tj = 0; tj < 4; tj++) {
                const uint32_t* bp = &bh[tj >> 1][(tj & 1) * 2];
                mma16816h(acc[ti][tj], ah[ti], bp);
            }
    }
}

// ---------------- batched GEMM: fp16 outputs, double-buffered weights ----------------
struct TcArgs {
    const float* A1;
    const float* A2;
    const char* wh[7];
    const float* b[7];
    __half* C[7];
    int nW1, nW2, M;
};

__global__ void __launch_bounds__(NT, 1) gemm_mma(TcArgs ga) {
    extern __shared__ char sm[];
    const uint32_t smb = smem_u32(sm);
    const int tid = threadIdx.x;
    const int wid = tid >> 5;
    const int lane = tid & 31;
    const int m0 = blockIdx.x * 128;
    const int M = ga.M;
    const int wm = wid >> 2;
    const int wn = wid & 3;
    const int sub = lane & 7;
    const int quad = lane >> 3;
    const int arow0 = wm * 32 + sub + (quad & 1) * 8;
    const int akb   = (quad >> 1) * 16;
    const int brow0 = wn * 32 + sub + (quad >> 1) * 8;
    const int bkb   = (quad & 1) * 16;
    const int g = lane >> 2;
    const int tg = lane & 3;

    const int nWtot = ga.nW1 + ga.nW2;

    // prologue: async-fetch weight 0, convert first A tile
    prefetch_w(smb + SW0, ga.wh[0], tid);
    conv_tile(ga.A1, m0, M, sm + SA, tid);

    int cur = 0;
    for (int w = 0; w < nWtot; w++) {
        CP_WAIT0();
        __syncthreads();                  // weight buf(cur) + A tile visible

        if (w == ga.nW1) {
            // switch A operand to A2 (prior gemm readers of SA passed the sync)
            conv_tile(ga.A2, m0, M, sm + SA, tid);
        }
        if (w + 1 < nWtot)
            prefetch_w(smb + SW0 + (cur ^ 1) * 32768, ga.wh[w + 1], tid);
        if (w == ga.nW1)
            __syncthreads();              // new A tile visible

        float acc[2][4][4];
        gemm_core(smb, SW0 + cur * 32768, acc, arow0, akb, brow0, bkb);

        // store fp16 C tile (+bias via __ldg; bias is 512B, L2-broadcast)
        const float* bias = ga.b[w];
        __half* __restrict__ C = ga.C[w];
#pragma unroll
        for (int ti = 0; ti < 2; ti++)
#pragma unroll
            for (int tj = 0; tj < 4; tj++) {
                int row = m0 + wm * 32 + ti * 16 + g;
                int col = wn * 32 + tj * 8 + tg * 2;
                float2 bv = bias ? *(const float2*)(bias + col) : make_float2(0.f, 0.f);
                if (row < M)
                    *(__half2*)(C + (size_t)row * Hd + col) =
                        __floats2half2_rn(acc[ti][tj][0] + bv.x, acc[ti][tj][1] + bv.y);
                if (row + 8 < M)
                    *(__half2*)(C + (size_t)(row + 8) * Hd + col) =
                        __floats2half2_rn(acc[ti][tj][2] + bv.x, acc[ti][tj][3] + bv.y);
            }
        cur ^= 1;
        __syncthreads();                  // all reads of buf(cur^1) done before its refill next iter
    }
}

// ---------------- epilogue: gates -> h, c ----------------
__global__ void epilogue_kernel(float* __restrict__ outh, float* __restrict__ outc, int n4) {
    int stride = gridDim.x * blockDim.x;
    for (int i = blockIdx.x * blockDim.x + threadIdx.x; i < n4; i += stride) {
        size_t e = (size_t)i * 4;
        float4 wix = ld_half4(g_Wixh + e);
        float4 uih = ld_half4(g_Uihh + e);
        float4 wcx = ld_half4(g_Wcxh + e);
        float4 uch = ld_half4(g_Uchh + e);
        float4 wox = ld_half4(g_Woxh + e);
        float4 uoh = ld_half4(g_Uohh + e);
        float4 sf  = ((const float4*)g_sumfc)[i];

        float4 hc, cc;
        {
            float ig = sigm_f(wix.x + uih.x);
            float ct = tanh_f(wcx.x + uch.x);
            float cval = fmaf(ig, ct, sf.x);
            float og = sigm_f(wox.x + uoh.x);
            cc.x = cval; hc.x = og * tanh_f(cval);
        }
        {
            float ig = sigm_f(wix.y + uih.y);
            float ct = tanh_f(wcx.y + uch.y);
            float cval = fmaf(ig, ct, sf.y);
            float og = sigm_f(wox.y + uoh.y);
            cc.y = cval; hc.y = og * tanh_f(cval);
        }
        {
            float ig = sigm_f(wix.z + uih.z);
            float ct = tanh_f(wcx.z + uch.z);
            float cval = fmaf(ig, ct, sf.z);
            float og = sigm_f(wox.z + uoh.z);
            cc.z = cval; hc.z = og * tanh_f(cval);
        }
        {
            float ig = sigm_f(wix.w + uih.w);
            float ct = tanh_f(wcx.w + uch.w);
            float cval = fmaf(ig, ct, sf.w);
            float og = sigm_f(wox.w + uoh.w);
            cc.w = cval; hc.w = og * tanh_f(cval);
        }
        ((float4*)outh)[i] = hc;
        ((float4*)outc)[i] = cc;
    }
}

// ---------------- launch ----------------
extern "C" void kernel_launch(void* const* d_in, const int* in_sizes, int n_in,
                              void* d_out, int out_size) {
    const float* x_emb   = (const float*)d_in[0];
    const float* child_h = (const float*)d_in[1];
    const float* child_c = (const float*)d_in[2];
    const int*   ci      = (const int*)d_in[3];
    const int*   chi     = (const int*)d_in[4];
    const float* Wi_w = (const float*)d_in[5];
    const float* Ui_w = (const float*)d_in[6];
    const float* Wf_w = (const float*)d_in[7];
    const float* Uf_w = (const float*)d_in[8];
    const float* Wo_w = (const float*)d_in[9];
    const float* Uo_w = (const float*)d_in[10];
    const float* Wc_w = (const float*)d_in[11];
    const float* Uc_w = (const float*)d_in[12];
    const float* Wa_w = (const float*)d_in[13];
    const float* Ua_w = (const float*)d_in[14];
    const float* Wi_b = (const float*)d_in[15];
    const float* Wf_b = (const float*)d_in[16];
    const float* Wo_b = (const float*)d_in[17];
    const float* Wc_b = (const float*)d_in[18];
    const float* Wa_b = (const float*)d_in[19];
    const float* v_w  = (const float*)d_in[20];

    const int M = in_sizes[0] / Hd;
    const int L = in_sizes[3];

    float *p_hhat;
    cudaGetSymbolAddress((void**)&p_hhat, g_hhat);
    __half *p_Ahh, *p_Bxh, *p_Wfxh, *p_Ufhh, *p_Wixh, *p_Woxh, *p_Wcxh, *p_Uihh, *p_Uchh, *p_Uohh;
    cudaGetSymbolAddress((void**)&p_Ahh,  g_Ahh);
    cudaGetSymbolAddress((void**)&p_Bxh,  g_Bxh);
    cudaGetSymbolAddress((void**)&p_Wfxh, g_Wfxh);
    cudaGetSymbolAddress((void**)&p_Ufhh, g_Ufhh);
    cudaGetSymbolAddress((void**)&p_Wixh, g_Wixh);
    cudaGetSymbolAddress((void**)&p_Woxh, g_Woxh);
    cudaGetSymbolAddress((void**)&p_Wcxh, g_Wcxh);
    cudaGetSymbolAddress((void**)&p_Uihh, g_Uihh);
    cudaGetSymbolAddress((void**)&p_Uchh, g_Uchh);
    cudaGetSymbolAddress((void**)&p_Uohh, g_Uohh);
    char *p_wh;
    cudaGetSymbolAddress((void**)&p_wh, g_Wbh);

    float* outh = (float*)d_out;
    float* outc = outh + (size_t)M * Hd;

    const int mtiles = (M + 127) / 128;
    const int nblk = (MAXM + 1023) / 1024;

    cudaFuncSetAttribute(gemm_mma, cudaFuncAttributeMaxDynamicSharedMemorySize, S_TOT1);

    // one-time side stream + events (host resources; identical work per call)
    static cudaStream_t s2 = nullptr;
    static cudaEvent_t evF = nullptr, evSort = nullptr, evG1 = nullptr, evFG = nullptr;
    if (!s2) {
        cudaStreamCreateWithFlags(&s2, cudaStreamNonBlocking);
        cudaEventCreateWithFlags(&evF,    cudaEventDisableTiming);
        cudaEventCreateWithFlags(&evSort, cudaEventDisableTiming);
        cudaEventCreateWithFlags(&evG1,   cudaEventDisableTiming);
        cudaEventCreateWithFlags(&evFG,   cudaEventDisableTiming);
    }

    // fork: side stream does shadows + counting sort (hidden under GEMM1)
    cudaEventRecord(evF, 0);
    cudaStreamWaitEvent(s2, evF, 0);
    side_kernel<<<296, 256, 0, s2>>>(child_h, child_c, M);
    hist_kernel<<<296, 256, 0, s2>>>(ci, L);
    scan1_kernel<<<nblk, 256, 0, s2>>>();
    scan2_kernel<<<1, 32, 0, s2>>>(nblk);
    fixup_kernel<<<64, 256, 0, s2>>>();
    scatter_kernel<<<296, 256, 0, s2>>>(ci, L);
    cudaEventRecord(evSort, s2);

    // main stream: weights prep + phase-1 GEMMs
    {
        PrepArgs pa;
        pa.W[0] = Ua_w; pa.W[1] = Wi_w; pa.W[2] = Wf_w; pa.W[3] = Wo_w; pa.W[4] = Wc_w;
        pa.W[5] = Wa_w; pa.W[6] = Uf_w; pa.W[7] = Ui_w; pa.W[8] = Uc_w; pa.W[9] = Uo_w;
        prep_w_kernel<<<148, 256>>>(pa);
    }
    {
        TcArgs ga;
        ga.A1 = x_emb; ga.A2 = child_h; ga.nW1 = 5; ga.nW2 = 2; ga.M = M;
        int slot[7] = {0, 1, 2, 3, 4, 5, 6};
        const float* bs[7] = {nullptr, Wi_b, Wf_b, Wo_b, Wc_b, Wa_b, nullptr};
        __half* cs[7] = {p_Bxh, p_Wixh, p_Wfxh, p_Woxh, p_Wcxh, p_Ahh, p_Ufhh};
        for (int i = 0; i < 7; i++) {
            ga.wh[i] = p_wh + slot[i] * 32768;
            ga.b[i] = bs[i];
            ga.C[i] = cs[i];
        }
        gemm_mma<<<mtiles, NT, S_TOT1>>>(ga);
    }
    cudaEventRecord(evG1, 0);

    // side stream: seg_forget (needs GEMM1 outputs + sort), overlaps seg_attn + GEMM3
    cudaStreamWaitEvent(s2, evG1, 0);
    seg_forget_kernel<<<(M + 7) / 8, 256, 0, s2>>>(chi, M);
    cudaEventRecord(evFG, s2);

    // main stream: seg_attn (needs sort results) then phase-3 GEMMs
    cudaStreamWaitEvent(0, evSort, 0);
    seg_attn_kernel<<<(M + 7) / 8, 256>>>(chi, v_w, M);

    {
        TcArgs ga;
        ga.A1 = p_hhat; ga.A2 = nullptr; ga.nW1 = 3; ga.nW2 = 0; ga.M = M;
        int slot[7] = {7, 8, 9, 7, 7, 7, 7};
        __half* cs[7] = {p_Uihh, p_Uchh, p_Uohh, p_Uihh, p_Uihh, p_Uihh, p_Uihh};
        for (int i = 0; i < 7; i++) {
            ga.wh[i] = p_wh + slot[i] * 32768;
            ga.b[i] = nullptr;
            ga.C[i] = cs[i];
        }
        gemm_mma<<<mtiles, NT, S_TOT1>>>(ga);
    }

    // join: epilogue needs GEMM3 outputs + sumfc from seg_forget
    cudaStreamWaitEvent(0, evFG, 0);
    const int n4 = M * Hd / 4;
    epilogue_kernel<<<(n4 + 255) / 256, 256>>>(outh, outc, n4);
}